// round 11
// baseline (speedup 1.0000x reference)
#include <cuda_runtime.h>
#include <cuda_bf16.h>
#include <math.h>
#include <stdint.h>

// ---------------------------------------------------------------------------
// Problem constants
// ---------------------------------------------------------------------------
#define T_TOK 16384          // B*N tokens
#define D_DIM 768
#define HID_DIM 3072
#define NHEAD 12
#define QKV_N 2304
#define K3_D 2304            // 3*768   (hi|lo|hi packed K)
#define K3_H 9216            // 3*3072
#define BH   192             // B*H

// ---------------------------------------------------------------------------
// Scratch (device globals; allocation-free per harness rules)
// ---------------------------------------------------------------------------
__device__ __align__(256) __nv_bfloat16 g_a3  [(size_t)T_TOK * K3_D];
__device__ __align__(256) __nv_bfloat16 g_h3  [(size_t)T_TOK * K3_H];
__device__ __align__(256) __nv_bfloat16 g_q3  [(size_t)BH * 1024 * 192];
__device__ __align__(256) __nv_bfloat16 g_k3  [(size_t)BH * 1024 * 192];
__device__ __align__(256) __nv_bfloat16 g_v3  [(size_t)BH * 16 * 64 * 192];
__device__ __align__(256) __nv_bfloat16 g_wqkv3 [(size_t)QKV_N  * K3_D];
__device__ __align__(256) __nv_bfloat16 g_wproj3[(size_t)D_DIM  * K3_D];
__device__ __align__(256) __nv_bfloat16 g_wfc13 [(size_t)HID_DIM* K3_D];
__device__ __align__(256) __nv_bfloat16 g_wfc23 [(size_t)D_DIM  * K3_H];

// ---------------------------------------------------------------------------
// PTX helpers (portable: cp.async / ldmatrix / mma.sync)
// ---------------------------------------------------------------------------
__device__ __forceinline__ uint32_t smem_u32(const void* p) {
    uint32_t a;
    asm("{ .reg .u64 t; cvta.to.shared.u64 t, %1; cvt.u32.u64 %0, t; }" : "=r"(a) : "l"(p));
    return a;
}

__device__ __forceinline__ void cp16(uint32_t saddr, const void* gaddr) {
    asm volatile("cp.async.cg.shared.global [%0], [%1], 16;" :: "r"(saddr), "l"(gaddr));
}
#define CP_COMMIT() asm volatile("cp.async.commit_group;" ::: "memory")
#define CP_WAIT2()  asm volatile("cp.async.wait_group 2;" ::: "memory")
#define CP_WAIT0()  asm volatile("cp.async.wait_group 0;" ::: "memory")

__device__ __forceinline__ void ldsm4(uint32_t* r, uint32_t addr) {
    asm volatile("ldmatrix.sync.aligned.m8n8.x4.shared.b16 {%0,%1,%2,%3}, [%4];"
                 : "=r"(r[0]), "=r"(r[1]), "=r"(r[2]), "=r"(r[3]) : "r"(addr));
}

__device__ __forceinline__ void mma16816(float* c, const uint32_t* a,
                                         uint32_t b0, uint32_t b1) {
    asm volatile(
        "mma.sync.aligned.m16n8k16.row.col.f32.bf16.bf16.f32 "
        "{%0,%1,%2,%3}, {%4,%5,%6,%7}, {%8,%9}, {%0,%1,%2,%3};"
        : "+f"(c[0]), "+f"(c[1]), "+f"(c[2]), "+f"(c[3])
        : "r"(a[0]), "r"(a[1]), "r"(a[2]), "r"(a[3]), "r"(b0), "r"(b1));
}

__device__ __forceinline__ void split2(float x, __nv_bfloat16& hi, __nv_bfloat16& lo) {
    hi = __float2bfloat16(x);
    lo = __float2bfloat16(x - __bfloat162float(hi));
}

// ---------------------------------------------------------------------------
// Weight pack: W[N,K] fp32 -> W3[N,3K] bf16 as [hi | hi | lo]
// ---------------------------------------------------------------------------
__global__ __launch_bounds__(256) void pack_w_kernel(
    const float* __restrict__ W, __nv_bfloat16* __restrict__ W3, int NK, int K)
{
    int idx = blockIdx.x * 256 + threadIdx.x;
    if (idx >= NK) return;
    int n = idx / K, k = idx - n * K;
    __nv_bfloat16 hi, lo;
    split2(W[idx], hi, lo);
    size_t base = (size_t)n * 3 * K + k;
    W3[base] = hi; W3[base + K] = hi; W3[base + 2 * K] = lo;
}

// ---------------------------------------------------------------------------
// Fused LayerNorm + activation pack: out3[t, 3*768] = [hi | lo | hi]
// ---------------------------------------------------------------------------
__global__ __launch_bounds__(256) void ln_pack_kernel(
    const float* __restrict__ x, const float* __restrict__ gam,
    const float* __restrict__ bet, __nv_bfloat16* __restrict__ out3)
{
    const int row = blockIdx.x;
    const int tid = threadIdx.x;
    const float* xr = x + (size_t)row * D_DIM;
    float v0 = xr[tid], v1 = xr[tid + 256], v2 = xr[tid + 512];
    float s = v0 + v1 + v2;
    float q = v0 * v0 + v1 * v1 + v2 * v2;

    __shared__ float sred[8], qred[8];
#pragma unroll
    for (int o = 16; o > 0; o >>= 1) {
        s += __shfl_xor_sync(0xffffffffu, s, o);
        q += __shfl_xor_sync(0xffffffffu, q, o);
    }
    if ((tid & 31) == 0) { sred[tid >> 5] = s; qred[tid >> 5] = q; }
    __syncthreads();
    s = 0.f; q = 0.f;
#pragma unroll
    for (int i = 0; i < 8; i++) { s += sred[i]; q += qred[i]; }
    const float mean = s * (1.0f / 768.0f);
    const float var  = q * (1.0f / 768.0f) - mean * mean;
    const float rstd = rsqrtf(var + 1e-6f);

    __nv_bfloat16* orow = out3 + (size_t)row * K3_D;
#pragma unroll
    for (int e = 0; e < 3; e++) {
        const int c = tid + e * 256;
        const float v = (e == 0 ? v0 : (e == 1 ? v1 : v2));
        const float y = (v - mean) * rstd * gam[c] + bet[c];
        __nv_bfloat16 hi, lo;
        split2(y, hi, lo);
        orow[c] = hi; orow[c + D_DIM] = lo; orow[c + 2 * D_DIM] = hi;
    }
}

// ---------------------------------------------------------------------------
// HMMA GEMM (NT): C[M,Nf] = A3[M,K3] * B3[Nf,K3]^T  (bf16 in, fp32 accum)
// CTA 128x256, BK=32, 8 warps as 2(m)x4(n), warp tile 64x64,
// 4-stage cp.async pipeline, ONE __syncthreads per iter.
// EPI: 1 = qkv split-pack into Q3/K3/V3; 2 = bias+GELU -> packed [hi|lo|hi];
//      3 = bias + residual -> fp32
// ---------------------------------------------------------------------------
#define STG_A_BYTES (128 * 80)           // 10240
#define STG_BYTES   (128 * 80 + 256 * 80) // 30720
#define NSTAGE 4
#define HG_SMEM (NSTAGE * STG_BYTES)     // 122880

template <int EPI>
__global__ __launch_bounds__(256) void hgemm_kernel(
    const __nv_bfloat16* __restrict__ A3, const __nv_bfloat16* __restrict__ B3,
    const float* __restrict__ bias, const float* __restrict__ resid,
    float* __restrict__ Cf, __nv_bfloat16* __restrict__ Cp,
    __nv_bfloat16* __restrict__ Q3o, __nv_bfloat16* __restrict__ K3o,
    __nv_bfloat16* __restrict__ V3o,
    int K3, int ldN)
{
    extern __shared__ __align__(128) char smraw[];
    const uint32_t su = smem_u32(smraw);

    const int tid  = threadIdx.x;
    const int wid  = tid >> 5;
    const int lane = tid & 31;
    const int wm   = wid >> 2;          // 0..1  (64-row slice)
    const int wn   = wid & 3;           // 0..3  (64-col slice)

    const int m0 = blockIdx.y * 128;
    const int n0 = blockIdx.x * 256;

    // A: 2 threads per row (32B each); B: 1 thread per row (64B)
    const int grow  = tid >> 1;
    const int ghalf = tid & 1;
    const __nv_bfloat16* ga = A3 + (size_t)(m0 + grow) * K3 + ghalf * 16;
    const __nv_bfloat16* gb = B3 + (size_t)(n0 + tid) * K3;
    const uint32_t a_st = grow * 80 + ghalf * 32;
    const uint32_t b_st = STG_A_BYTES + tid * 80;

    const uint32_t lrow  = lane & 15;
    const uint32_t lcolb = (lane >> 4) * 16;
    const uint32_t a_ld  = (wm * 64 + lrow) * 80 + lcolb;
    const uint32_t b_ld  = STG_A_BYTES + (wn * 64 + lrow) * 80 + lcolb;

    float acc[4][8][4];
#pragma unroll
    for (int i = 0; i < 4; i++)
#pragma unroll
        for (int j = 0; j < 8; j++)
#pragma unroll
            for (int v = 0; v < 4; v++) acc[i][j][v] = 0.f;

    const int Tn = K3 / 32;

    // Prologue: stages 0..2
#pragma unroll
    for (int s = 0; s < NSTAGE - 1; s++) {
        const uint32_t sb = su + s * STG_BYTES;
        const __nv_bfloat16* ga2 = ga + s * 32;
        const __nv_bfloat16* gb2 = gb + s * 32;
        cp16(sb + a_st, ga2);          cp16(sb + a_st + 16, ga2 + 8);
#pragma unroll
        for (int j = 0; j < 4; j++)
            cp16(sb + b_st + j * 16, gb2 + j * 8);
        CP_COMMIT();
    }

    for (int t = 0; t < Tn; t++) {
        CP_WAIT2();
        __syncthreads();

        const uint32_t stg = su + (t & (NSTAGE - 1)) * STG_BYTES;
        const uint32_t abase = stg + a_ld;
        const uint32_t bbase = stg + b_ld;
#pragma unroll
        for (int ks = 0; ks < 2; ks++) {
            uint32_t af[4][4], bfr[4][4];
#pragma unroll
            for (int mi = 0; mi < 4; mi++)
                ldsm4(af[mi], abase + mi * 16 * 80 + ks * 32);
#pragma unroll
            for (int ni = 0; ni < 4; ni++)
                ldsm4(bfr[ni], bbase + ni * 16 * 80 + ks * 32);
#pragma unroll
            for (int mi = 0; mi < 4; mi++)
#pragma unroll
                for (int ni = 0; ni < 4; ni++) {
                    mma16816(acc[mi][2 * ni],     af[mi], bfr[ni][0], bfr[ni][2]);
                    mma16816(acc[mi][2 * ni + 1], af[mi], bfr[ni][1], bfr[ni][3]);
                }
        }

        // Prefetch stage t+3 (writes buffer consumed at iter t-1; safe after
        // this iter's top __syncthreads). Always commit (empty group at tail
        // keeps wait_group bookkeeping exact).
        const int tp = t + NSTAGE - 1;
        if (tp < Tn) {
            const uint32_t sb = su + (tp & (NSTAGE - 1)) * STG_BYTES;
            const __nv_bfloat16* ga2 = ga + tp * 32;
            const __nv_bfloat16* gb2 = gb + tp * 32;
            cp16(sb + a_st, ga2);          cp16(sb + a_st + 16, ga2 + 8);
#pragma unroll
            for (int j = 0; j < 4; j++)
                cp16(sb + b_st + j * 16, gb2 + j * 8);
        }
        CP_COMMIT();
    }

    // -------------------- Epilogue --------------------
    const int lm = lane >> 2;
    const int lc = (lane & 3) * 2;

#pragma unroll
    for (int mi = 0; mi < 4; mi++) {
#pragma unroll
        for (int nj = 0; nj < 8; nj++) {
            const int row = m0 + wm * 64 + mi * 16 + lm;
            const int col = n0 + wn * 64 + nj * 8 + lc;
            const float* c = acc[mi][nj];
#pragma unroll
            for (int h = 0; h < 2; h++) {
                const int r = row + h * 8;
                float v0 = c[2 * h], v1 = c[2 * h + 1];
                if (EPI == 3) {
                    const float2 rr = *(const float2*)(resid + (size_t)r * ldN + col);
                    float2 o;
                    o.x = v0 + bias[col]     + rr.x;
                    o.y = v1 + bias[col + 1] + rr.y;
                    *(float2*)(Cf + (size_t)r * ldN + col) = o;
                } else if (EPI == 2) {
                    v0 += bias[col];
                    v1 += bias[col + 1];
                    v0 = 0.5f * v0 * (1.0f + erff(v0 * 0.70710678118654752f));
                    v1 = 0.5f * v1 * (1.0f + erff(v1 * 0.70710678118654752f));
                    __nv_bfloat16 h0, l0, h1, l1;
                    split2(v0, h0, l0); split2(v1, h1, l1);
                    __nv_bfloat162 hh, ll;
                    hh.x = h0; hh.y = h1; ll.x = l0; ll.y = l1;
                    __nv_bfloat16* rb = Cp + (size_t)r * (3 * (size_t)ldN);
                    *(__nv_bfloat162*)(rb + col)            = hh;
                    *(__nv_bfloat162*)(rb + ldN + col)      = ll;
                    *(__nv_bfloat162*)(rb + 2 * ldN + col)  = hh;
                } else {  // EPI == 1: split-pack Q/K/V attention operands
                    const int b  = r >> 10, n = r & 1023;
                    const int which = col / 768;
                    const int rem = col - which * 768;
                    const int hh_ = rem >> 6, d = rem & 63;
                    const int bh = b * NHEAD + hh_;
                    __nv_bfloat16 h0, l0, h1, l1;
                    split2(v0, h0, l0); split2(v1, h1, l1);
                    __nv_bfloat162 hp, lp;
                    hp.x = h0; hp.y = h1; lp.x = l0; lp.y = l1;
                    if (which == 0) {          // Q: [hi | lo | hi]
                        __nv_bfloat16* base = Q3o + ((size_t)bh * 1024 + n) * 192;
                        *(__nv_bfloat162*)(base + d)       = hp;
                        *(__nv_bfloat162*)(base + 64 + d)  = lp;
                        *(__nv_bfloat162*)(base + 128 + d) = hp;
                    } else if (which == 1) {   // K: [hi | hi | lo]
                        __nv_bfloat16* base = K3o + ((size_t)bh * 1024 + n) * 192;
                        *(__nv_bfloat162*)(base + d)       = hp;
                        *(__nv_bfloat162*)(base + 64 + d)  = hp;
                        *(__nv_bfloat162*)(base + 128 + d) = lp;
                    } else {                   // V tile [(bh,kt)][64 d][hi|hi|lo over j]
                        const int kt = n >> 6, j = n & 63;
                        __nv_bfloat16* tb = V3o + ((size_t)(bh * 16 + kt) * 64) * 192;
                        __nv_bfloat16* r0p = tb + (size_t)d * 192;
                        __nv_bfloat16* r1p = r0p + 192;
                        r0p[j] = h0; r0p[64 + j] = h0; r0p[128 + j] = l0;
                        r1p[j] = h1; r1p[64 + j] = h1; r1p[128 + j] = l1;
                    }
                }
            }
        }
    }
}

// ---------------------------------------------------------------------------
// Tensor-core flash attention. grid (16 qtiles, 192 bh), 128 threads / 4 warps.
// ---------------------------------------------------------------------------
#define ATT_STRIDE 200       // elems per smem row (400 B)
#define ATT_TILE   (64 * ATT_STRIDE)
#define ATT_SMEM   (4 * ATT_TILE * 2)

__global__ __launch_bounds__(128) void fattn_kernel(
    const __nv_bfloat16* __restrict__ q3, const __nv_bfloat16* __restrict__ k3,
    const __nv_bfloat16* __restrict__ v3, __nv_bfloat16* __restrict__ out3)
{
    extern __shared__ __nv_bfloat16 sm[];
    __nv_bfloat16* Qs = sm;
    __nv_bfloat16* Ks = Qs + ATT_TILE;
    __nv_bfloat16* Vs = Ks + ATT_TILE;
    __nv_bfloat16* Ps = Vs + ATT_TILE;

    const int tid = threadIdx.x, wid = tid >> 5, lane = tid & 31;
    const int qt = blockIdx.x, bh = blockIdx.y;
    const int q0 = qt * 64;

    const uint32_t qs_u = smem_u32(Qs);
    const uint32_t ks_u = smem_u32(Ks);
    const uint32_t vs_u = smem_u32(Vs);

    {
        const __nv_bfloat16* gQ = q3 + ((size_t)bh * 1024 + q0) * 192;
#pragma unroll
        for (int i = 0; i < 12; i++) {
            const int e = tid + i * 128;
            const int rw = e / 24, cc = e % 24;
            cp16(qs_u + rw * 400 + cc * 16, gQ + rw * 192 + cc * 8);
        }
    }
    CP_COMMIT();

    const uint32_t lrow = lane & 15;
    const uint32_t lcolb = (lane >> 4) * 16;
    const uint32_t a_q = qs_u + (wid * 16 + lrow) * 400 + lcolb;
    const uint32_t a_p = smem_u32(Ps) + (wid * 16 + lrow) * 400 + lcolb;

    float mrun[2] = {-1e30f, -1e30f}, lrun[2] = {0.f, 0.f};
    float accO[8][4];
#pragma unroll
    for (int f = 0; f < 8; f++)
#pragma unroll
        for (int v = 0; v < 4; v++) accO[f][v] = 0.f;

    for (int kt = 0; kt < 16; kt++) {
        __syncthreads();
        {
            const __nv_bfloat16* gK = k3 + ((size_t)bh * 1024 + kt * 64) * 192;
            const __nv_bfloat16* gV = v3 + ((size_t)(bh * 16 + kt) * 64) * 192;
#pragma unroll
            for (int i = 0; i < 12; i++) {
                const int e = tid + i * 128;
                const int rw = e / 24, cc = e % 24;
                cp16(ks_u + rw * 400 + cc * 16, gK + rw * 192 + cc * 8);
                cp16(vs_u + rw * 400 + cc * 16, gV + rw * 192 + cc * 8);
            }
        }
        CP_COMMIT();
        CP_WAIT0();
        __syncthreads();

        float sacc[8][4];
#pragma unroll
        for (int f = 0; f < 8; f++)
#pragma unroll
            for (int v = 0; v < 4; v++) sacc[f][v] = 0.f;
#pragma unroll
        for (int ks = 0; ks < 12; ks++) {
            uint32_t af[4], bfr[4][4];
            ldsm4(af, a_q + ks * 32);
#pragma unroll
            for (int ni = 0; ni < 4; ni++)
                ldsm4(bfr[ni], ks_u + (ni * 16 + lrow) * 400 + lcolb + ks * 32);
#pragma unroll
            for (int ni = 0; ni < 4; ni++) {
                mma16816(sacc[2 * ni],     af, bfr[ni][0], bfr[ni][2]);
                mma16816(sacc[2 * ni + 1], af, bfr[ni][1], bfr[ni][3]);
            }
        }
#pragma unroll
        for (int f = 0; f < 8; f++)
#pragma unroll
            for (int v = 0; v < 4; v++) sacc[f][v] *= 0.125f;

#pragma unroll
        for (int hf = 0; hf < 2; hf++) {
            float mt = -1e30f;
#pragma unroll
            for (int f = 0; f < 8; f++)
                mt = fmaxf(mt, fmaxf(sacc[f][2 * hf], sacc[f][2 * hf + 1]));
            mt = fmaxf(mt, __shfl_xor_sync(0xffffffffu, mt, 1));
            mt = fmaxf(mt, __shfl_xor_sync(0xffffffffu, mt, 2));
            const float mnew = fmaxf(mrun[hf], mt);
            const float corr = exp2f((mrun[hf] - mnew) * 1.4426950408889634f);
            float rs = 0.f;
            const int prow = wid * 16 + (lane >> 2) + hf * 8;
            __nv_bfloat16* pb = Ps + prow * ATT_STRIDE + (lane & 3) * 2;
#pragma unroll
            for (int f = 0; f < 8; f++) {
                float p0 = exp2f((sacc[f][2 * hf]     - mnew) * 1.4426950408889634f);
                float p1 = exp2f((sacc[f][2 * hf + 1] - mnew) * 1.4426950408889634f);
                rs += p0 + p1;
                __nv_bfloat16 h0, l0, h1, l1;
                split2(p0, h0, l0); split2(p1, h1, l1);
                __nv_bfloat162 hp, lp;
                hp.x = h0; hp.y = h1; lp.x = l0; lp.y = l1;
                *(__nv_bfloat162*)(pb + f * 8)        = hp;
                *(__nv_bfloat162*)(pb + 64 + f * 8)   = lp;
                *(__nv_bfloat162*)(pb + 128 + f * 8)  = hp;
            }
            rs += __shfl_xor_sync(0xffffffffu, rs, 1);
            rs += __shfl_xor_sync(0xffffffffu, rs, 2);
            lrun[hf] = lrun[hf] * corr + rs;
            mrun[hf] = mnew;
#pragma unroll
            for (int f = 0; f < 8; f++) {
                accO[f][2 * hf]     *= corr;
                accO[f][2 * hf + 1] *= corr;
            }
        }
        __syncthreads();

#pragma unroll
        for (int ks = 0; ks < 12; ks++) {
            uint32_t af[4], bfr[4][4];
            ldsm4(af, a_p + ks * 32);
#pragma unroll
            for (int ni = 0; ni < 4; ni++)
                ldsm4(bfr[ni], vs_u + (ni * 16 + lrow) * 400 + lcolb + ks * 32);
#pragma unroll
            for (int ni = 0; ni < 4; ni++) {
                mma16816(accO[2 * ni],     af, bfr[ni][0], bfr[ni][2]);
                mma16816(accO[2 * ni + 1], af, bfr[ni][1], bfr[ni][3]);
            }
        }
    }

    const int b = bh / NHEAD, h = bh - b * NHEAD;
#pragma unroll
    for (int hf = 0; hf < 2; hf++) {
        const float inv = 1.0f / lrun[hf];
        const int t = b * 1024 + q0 + wid * 16 + (lane >> 2) + hf * 8;
        __nv_bfloat16* orow = out3 + (size_t)t * K3_D;
        const int cbase = h * 64 + (lane & 3) * 2;
#pragma unroll
        for (int f = 0; f < 8; f++) {
            const float v0 = accO[f][2 * hf] * inv;
            const float v1 = accO[f][2 * hf + 1] * inv;
            __nv_bfloat16 h0, l0, h1, l1;
            split2(v0, h0, l0); split2(v1, h1, l1);
            __nv_bfloat162 hp, lp;
            hp.x = h0; hp.y = h1; lp.x = l0; lp.y = l1;
            const int c = cbase + f * 8;
            *(__nv_bfloat162*)(orow + c)             = hp;
            *(__nv_bfloat162*)(orow + c + D_DIM)     = lp;
            *(__nv_bfloat162*)(orow + c + 2 * D_DIM) = hp;
        }
    }
}

// ---------------------------------------------------------------------------
// Launch
// ---------------------------------------------------------------------------
extern "C" void kernel_launch(void* const* d_in, const int* in_sizes, int n_in,
                              void* d_out, int out_size)
{
    const float* x      = (const float*)d_in[0];
    const float* qkv_w  = (const float*)d_in[1];
    const float* proj_w = (const float*)d_in[2];
    const float* proj_b = (const float*)d_in[3];
    const float* fc1_w  = (const float*)d_in[4];
    const float* fc1_b  = (const float*)d_in[5];
    const float* fc2_w  = (const float*)d_in[6];
    const float* fc2_b  = (const float*)d_in[7];
    const float* n1g    = (const float*)d_in[8];
    const float* n1b    = (const float*)d_in[9];
    const float* n2g    = (const float*)d_in[10];
    const float* n2b    = (const float*)d_in[11];
    float* out = (float*)d_out;

    void *pa3, *ph3, *pq3, *pk3, *pv3, *pwq, *pwp, *pw1, *pw2;
    cudaGetSymbolAddress(&pa3, g_a3);
    cudaGetSymbolAddress(&ph3, g_h3);
    cudaGetSymbolAddress(&pq3, g_q3);
    cudaGetSymbolAddress(&pk3, g_k3);
    cudaGetSymbolAddress(&pv3, g_v3);
    cudaGetSymbolAddress(&pwq, g_wqkv3);
    cudaGetSymbolAddress(&pwp, g_wproj3);
    cudaGetSymbolAddress(&pw1, g_wfc13);
    cudaGetSymbolAddress(&pw2, g_wfc23);
    __nv_bfloat16* a3  = (__nv_bfloat16*)pa3;
    __nv_bfloat16* h3  = (__nv_bfloat16*)ph3;
    __nv_bfloat16* q3  = (__nv_bfloat16*)pq3;
    __nv_bfloat16* k3  = (__nv_bfloat16*)pk3;
    __nv_bfloat16* v3  = (__nv_bfloat16*)pv3;
    __nv_bfloat16* wq3 = (__nv_bfloat16*)pwq;
    __nv_bfloat16* wp3 = (__nv_bfloat16*)pwp;
    __nv_bfloat16* w13 = (__nv_bfloat16*)pw1;
    __nv_bfloat16* w23 = (__nv_bfloat16*)pw2;

    cudaFuncSetAttribute(hgemm_kernel<1>, cudaFuncAttributeMaxDynamicSharedMemorySize, HG_SMEM);
    cudaFuncSetAttribute(hgemm_kernel<2>, cudaFuncAttributeMaxDynamicSharedMemorySize, HG_SMEM);
    cudaFuncSetAttribute(hgemm_kernel<3>, cudaFuncAttributeMaxDynamicSharedMemorySize, HG_SMEM);
    cudaFuncSetAttribute(fattn_kernel, cudaFuncAttributeMaxDynamicSharedMemorySize, ATT_SMEM);

    // 0) pack weights (hi|hi|lo along K)
    pack_w_kernel<<<(QKV_N * D_DIM + 255) / 256, 256>>>(qkv_w,  wq3, QKV_N * D_DIM,  D_DIM);
    pack_w_kernel<<<(D_DIM * D_DIM + 255) / 256, 256>>>(proj_w, wp3, D_DIM * D_DIM,  D_DIM);
    pack_w_kernel<<<(HID_DIM * D_DIM + 255) / 256, 256>>>(fc1_w, w13, HID_DIM * D_DIM, D_DIM);
    pack_w_kernel<<<(D_DIM * HID_DIM + 255) / 256, 256>>>(fc2_w, w23, D_DIM * HID_DIM, HID_DIM);

    // 1) LN1 + pack (hi|lo|hi)
    ln_pack_kernel<<<T_TOK, 256>>>(x, n1g, n1b, a3);
    // 2) QKV GEMM -> split-packed Q3/K3/V3 attention operands
    hgemm_kernel<1><<<dim3(QKV_N / 256, T_TOK / 128), 256, HG_SMEM>>>(
        a3, wq3, nullptr, nullptr, nullptr, nullptr, q3, k3, v3, K3_D, QKV_N);
    // 3) tensor-core flash attention -> packed a3
    fattn_kernel<<<dim3(16, BH), 128, ATT_SMEM>>>(q3, k3, v3, a3);
    // 4) x1 = x + attn @ proj_w^T + proj_b -> d_out
    hgemm_kernel<3><<<dim3(D_DIM / 256, T_TOK / 128), 256, HG_SMEM>>>(
        a3, wp3, proj_b, x, out, nullptr, nullptr, nullptr, nullptr, K3_D, D_DIM);
    // 5) LN2 + pack
    ln_pack_kernel<<<T_TOK, 256>>>(out, n2g, n2b, a3);
    // 6) h3 = pack(gelu(ln2 @ fc1_w^T + fc1_b))
    hgemm_kernel<2><<<dim3(HID_DIM / 256, T_TOK / 128), 256, HG_SMEM>>>(
        a3, w13, fc1_b, nullptr, nullptr, h3, nullptr, nullptr, nullptr, K3_D, HID_DIM);
    // 7) out = x1 + h @ fc2_w^T + fc2_b (in-place residual)
    hgemm_kernel<3><<<dim3(D_DIM / 256, T_TOK / 128), 256, HG_SMEM>>>(
        h3, w23, fc2_b, out, out, nullptr, nullptr, nullptr, nullptr, K3_H, D_DIM);
}

// round 14
// speedup vs baseline: 1.2081x; 1.2081x over previous
#include <cuda_runtime.h>
#include <cuda_bf16.h>
#include <math.h>
#include <stdint.h>

// ---------------------------------------------------------------------------
// Problem constants
// ---------------------------------------------------------------------------
#define T_TOK 16384          // B*N tokens
#define D_DIM 768
#define HID_DIM 3072
#define NHEAD 12
#define QKV_N 2304
#define K3_D 2304            // 3*768   (hi|lo|hi packed K)
#define K3_H 9216            // 3*3072
#define BH   192             // B*H

// ---------------------------------------------------------------------------
// Scratch (device globals; allocation-free per harness rules)
// ---------------------------------------------------------------------------
__device__ __align__(256) __nv_bfloat16 g_a3  [(size_t)T_TOK * K3_D];
__device__ __align__(256) __nv_bfloat16 g_h3  [(size_t)T_TOK * K3_H];
__device__ __align__(256) __nv_bfloat16 g_q3  [(size_t)BH * 1024 * 192];
__device__ __align__(256) __nv_bfloat16 g_k3  [(size_t)BH * 1024 * 192];
__device__ __align__(256) __nv_bfloat16 g_v3  [(size_t)BH * 16 * 64 * 192];
__device__ __align__(256) __nv_bfloat16 g_wqkv3 [(size_t)QKV_N  * K3_D];
__device__ __align__(256) __nv_bfloat16 g_wproj3[(size_t)D_DIM  * K3_D];
__device__ __align__(256) __nv_bfloat16 g_wfc13 [(size_t)HID_DIM* K3_D];
__device__ __align__(256) __nv_bfloat16 g_wfc23 [(size_t)D_DIM  * K3_H];

// ---------------------------------------------------------------------------
// PTX helpers (portable: cp.async / ldmatrix / mma.sync)
// ---------------------------------------------------------------------------
__device__ __forceinline__ uint32_t smem_u32(const void* p) {
    uint32_t a;
    asm("{ .reg .u64 t; cvta.to.shared.u64 t, %1; cvt.u32.u64 %0, t; }" : "=r"(a) : "l"(p));
    return a;
}

__device__ __forceinline__ void cp16(uint32_t saddr, const void* gaddr) {
    asm volatile("cp.async.cg.shared.global [%0], [%1], 16;" :: "r"(saddr), "l"(gaddr));
}
#define CP_COMMIT() asm volatile("cp.async.commit_group;" ::: "memory")
#define CP_WAIT1()  asm volatile("cp.async.wait_group 1;" ::: "memory")
#define CP_WAIT0()  asm volatile("cp.async.wait_group 0;" ::: "memory")

__device__ __forceinline__ void ldsm4(uint32_t* r, uint32_t addr) {
    asm volatile("ldmatrix.sync.aligned.m8n8.x4.shared.b16 {%0,%1,%2,%3}, [%4];"
                 : "=r"(r[0]), "=r"(r[1]), "=r"(r[2]), "=r"(r[3]) : "r"(addr));
}

__device__ __forceinline__ void mma16816(float* c, const uint32_t* a,
                                         uint32_t b0, uint32_t b1) {
    asm volatile(
        "mma.sync.aligned.m16n8k16.row.col.f32.bf16.bf16.f32 "
        "{%0,%1,%2,%3}, {%4,%5,%6,%7}, {%8,%9}, {%0,%1,%2,%3};"
        : "+f"(c[0]), "+f"(c[1]), "+f"(c[2]), "+f"(c[3])
        : "r"(a[0]), "r"(a[1]), "r"(a[2]), "r"(a[3]), "r"(b0), "r"(b1));
}

__device__ __forceinline__ void split2(float x, __nv_bfloat16& hi, __nv_bfloat16& lo) {
    hi = __float2bfloat16(x);
    lo = __float2bfloat16(x - __bfloat162float(hi));
}

// ---------------------------------------------------------------------------
// Weight pack: W[N,K] fp32 -> W3[N,3K] bf16 as [hi | hi | lo]
// ---------------------------------------------------------------------------
__global__ __launch_bounds__(256) void pack_w_kernel(
    const float* __restrict__ W, __nv_bfloat16* __restrict__ W3, int NK, int K)
{
    int idx = blockIdx.x * 256 + threadIdx.x;
    if (idx >= NK) return;
    int n = idx / K, k = idx - n * K;
    __nv_bfloat16 hi, lo;
    split2(W[idx], hi, lo);
    size_t base = (size_t)n * 3 * K + k;
    W3[base] = hi; W3[base + K] = hi; W3[base + 2 * K] = lo;
}

// ---------------------------------------------------------------------------
// Fused LayerNorm + activation pack: out3[t, 3*768] = [hi | lo | hi]
// ---------------------------------------------------------------------------
__global__ __launch_bounds__(256) void ln_pack_kernel(
    const float* __restrict__ x, const float* __restrict__ gam,
    const float* __restrict__ bet, __nv_bfloat16* __restrict__ out3)
{
    const int row = blockIdx.x;
    const int tid = threadIdx.x;
    const float* xr = x + (size_t)row * D_DIM;
    float v0 = xr[tid], v1 = xr[tid + 256], v2 = xr[tid + 512];
    float s = v0 + v1 + v2;
    float q = v0 * v0 + v1 * v1 + v2 * v2;

    __shared__ float sred[8], qred[8];
#pragma unroll
    for (int o = 16; o > 0; o >>= 1) {
        s += __shfl_xor_sync(0xffffffffu, s, o);
        q += __shfl_xor_sync(0xffffffffu, q, o);
    }
    if ((tid & 31) == 0) { sred[tid >> 5] = s; qred[tid >> 5] = q; }
    __syncthreads();
    s = 0.f; q = 0.f;
#pragma unroll
    for (int i = 0; i < 8; i++) { s += sred[i]; q += qred[i]; }
    const float mean = s * (1.0f / 768.0f);
    const float var  = q * (1.0f / 768.0f) - mean * mean;
    const float rstd = rsqrtf(var + 1e-6f);

    __nv_bfloat16* orow = out3 + (size_t)row * K3_D;
#pragma unroll
    for (int e = 0; e < 3; e++) {
        const int c = tid + e * 256;
        const float v = (e == 0 ? v0 : (e == 1 ? v1 : v2));
        const float y = (v - mean) * rstd * gam[c] + bet[c];
        __nv_bfloat16 hi, lo;
        split2(y, hi, lo);
        orow[c] = hi; orow[c + D_DIM] = lo; orow[c + 2 * D_DIM] = hi;
    }
}

// ---------------------------------------------------------------------------
// HMMA GEMM (NT): C[M,Nf] = A3[M,K3] * B3[Nf,K3]^T  (bf16 in, fp32 accum)
// CTA 128x256, BK=32, 512 threads / 16 warps as 4(m)x4(n), warp tile 32x64,
// 3-stage cp.async pipeline, ONE __syncthreads per iter.
// EPI: 1 = qkv split-pack into Q3/K3/V3; 2 = bias+GELU -> packed [hi|lo|hi];
//      3 = bias + residual -> fp32
// ---------------------------------------------------------------------------
#define STG_A_BYTES (128 * 80)            // 10240
#define STG_BYTES   (128 * 80 + 256 * 80) // 30720
#define NSTAGE 3
#define HG_SMEM (NSTAGE * STG_BYTES)      // 92160

template <int EPI>
__global__ __launch_bounds__(512) void hgemm_kernel(
    const __nv_bfloat16* __restrict__ A3, const __nv_bfloat16* __restrict__ B3,
    const float* __restrict__ bias, const float* __restrict__ resid,
    float* __restrict__ Cf, __nv_bfloat16* __restrict__ Cp,
    __nv_bfloat16* __restrict__ Q3o, __nv_bfloat16* __restrict__ K3o,
    __nv_bfloat16* __restrict__ V3o,
    int K3, int ldN)
{
    extern __shared__ __align__(128) char smraw[];
    const uint32_t su = smem_u32(smraw);

    const int tid  = threadIdx.x;
    const int wid  = tid >> 5;
    const int lane = tid & 31;
    const int wm   = wid >> 2;          // 0..3  (32-row slice)
    const int wn   = wid & 3;           // 0..3  (64-col slice)

    const int m0 = blockIdx.y * 128;
    const int n0 = blockIdx.x * 256;

    // A: 4 threads per row (16B each); B: 2 threads per row (32B each)
    const int arow = tid >> 2, aq = tid & 3;
    const int brow = tid >> 1, bhalf = tid & 1;
    const __nv_bfloat16* ga = A3 + (size_t)(m0 + arow) * K3 + aq * 8;
    const __nv_bfloat16* gb = B3 + (size_t)(n0 + brow) * K3 + bhalf * 16;
    const uint32_t a_st = arow * 80 + aq * 16;
    const uint32_t b_st = STG_A_BYTES + brow * 80 + bhalf * 32;

    const uint32_t lrow  = lane & 15;
    const uint32_t lcolb = (lane >> 4) * 16;
    const uint32_t a_ld  = (wm * 32 + lrow) * 80 + lcolb;
    const uint32_t b_ld  = STG_A_BYTES + (wn * 64 + lrow) * 80 + lcolb;

    float acc[2][8][4];
#pragma unroll
    for (int i = 0; i < 2; i++)
#pragma unroll
        for (int j = 0; j < 8; j++)
#pragma unroll
            for (int v = 0; v < 4; v++) acc[i][j][v] = 0.f;

    const int Tn = K3 / 32;

    // Prologue: stages 0..1
#pragma unroll
    for (int s = 0; s < NSTAGE - 1; s++) {
        const uint32_t sb = su + s * STG_BYTES;
        cp16(sb + a_st, ga + s * 32);
        cp16(sb + b_st,      gb + s * 32);
        cp16(sb + b_st + 16, gb + s * 32 + 8);
        CP_COMMIT();
    }

    int stg_idx = 0;
    for (int t = 0; t < Tn; t++) {
        CP_WAIT1();
        __syncthreads();

        const uint32_t stg = su + stg_idx * STG_BYTES;
        const uint32_t abase = stg + a_ld;
        const uint32_t bbase = stg + b_ld;
#pragma unroll
        for (int ks = 0; ks < 2; ks++) {
            uint32_t af[2][4], bfr[4][4];
            ldsm4(af[0], abase + ks * 32);
            ldsm4(af[1], abase + 16 * 80 + ks * 32);
#pragma unroll
            for (int ni = 0; ni < 4; ni++)
                ldsm4(bfr[ni], bbase + ni * 16 * 80 + ks * 32);
#pragma unroll
            for (int mi = 0; mi < 2; mi++)
#pragma unroll
                for (int ni = 0; ni < 4; ni++) {
                    mma16816(acc[mi][2 * ni],     af[mi], bfr[ni][0], bfr[ni][2]);
                    mma16816(acc[mi][2 * ni + 1], af[mi], bfr[ni][1], bfr[ni][3]);
                }
        }

        // Prefetch stage t+2 into the buffer consumed at iter t-1 (safe: the
        // top-of-iter __syncthreads ordered all its reads before this point).
        const int tp = t + NSTAGE - 1;
        if (tp < Tn) {
            int pidx = stg_idx + (NSTAGE - 1);
            if (pidx >= NSTAGE) pidx -= NSTAGE;
            const uint32_t sb = su + pidx * STG_BYTES;
            cp16(sb + a_st, ga + tp * 32);
            cp16(sb + b_st,      gb + tp * 32);
            cp16(sb + b_st + 16, gb + tp * 32 + 8);
        }
        CP_COMMIT();   // empty group at tail keeps wait_group bookkeeping exact

        if (++stg_idx == NSTAGE) stg_idx = 0;
    }

    // -------------------- Epilogue --------------------
    const int lm = lane >> 2;
    const int lc = (lane & 3) * 2;

#pragma unroll
    for (int mi = 0; mi < 2; mi++) {
#pragma unroll
        for (int nj = 0; nj < 8; nj++) {
            const int row = m0 + wm * 32 + mi * 16 + lm;
            const int col = n0 + wn * 64 + nj * 8 + lc;
            const float* c = acc[mi][nj];
#pragma unroll
            for (int h = 0; h < 2; h++) {
                const int r = row + h * 8;
                float v0 = c[2 * h], v1 = c[2 * h + 1];
                if (EPI == 3) {
                    const float2 rr = *(const float2*)(resid + (size_t)r * ldN + col);
                    float2 o;
                    o.x = v0 + bias[col]     + rr.x;
                    o.y = v1 + bias[col + 1] + rr.y;
                    *(float2*)(Cf + (size_t)r * ldN + col) = o;
                } else if (EPI == 2) {
                    v0 += bias[col];
                    v1 += bias[col + 1];
                    v0 = 0.5f * v0 * (1.0f + erff(v0 * 0.70710678118654752f));
                    v1 = 0.5f * v1 * (1.0f + erff(v1 * 0.70710678118654752f));
                    __nv_bfloat16 h0, l0, h1, l1;
                    split2(v0, h0, l0); split2(v1, h1, l1);
                    __nv_bfloat162 hh, ll;
                    hh.x = h0; hh.y = h1; ll.x = l0; ll.y = l1;
                    __nv_bfloat16* rb = Cp + (size_t)r * (3 * (size_t)ldN);
                    *(__nv_bfloat162*)(rb + col)            = hh;
                    *(__nv_bfloat162*)(rb + ldN + col)      = ll;
                    *(__nv_bfloat162*)(rb + 2 * ldN + col)  = hh;
                } else {  // EPI == 1: split-pack Q/K/V attention operands
                    const int b  = r >> 10, n = r & 1023;
                    const int which = col / 768;
                    const int rem = col - which * 768;
                    const int hh_ = rem >> 6, d = rem & 63;
                    const int bh = b * NHEAD + hh_;
                    __nv_bfloat16 h0, l0, h1, l1;
                    split2(v0, h0, l0); split2(v1, h1, l1);
                    __nv_bfloat162 hp, lp;
                    hp.x = h0; hp.y = h1; lp.x = l0; lp.y = l1;
                    if (which == 0) {          // Q: [hi | lo | hi]
                        __nv_bfloat16* base = Q3o + ((size_t)bh * 1024 + n) * 192;
                        *(__nv_bfloat162*)(base + d)       = hp;
                        *(__nv_bfloat162*)(base + 64 + d)  = lp;
                        *(__nv_bfloat162*)(base + 128 + d) = hp;
                    } else if (which == 1) {   // K: [hi | hi | lo]
                        __nv_bfloat16* base = K3o + ((size_t)bh * 1024 + n) * 192;
                        *(__nv_bfloat162*)(base + d)       = hp;
                        *(__nv_bfloat162*)(base + 64 + d)  = hp;
                        *(__nv_bfloat162*)(base + 128 + d) = lp;
                    } else {                   // V tile [(bh,kt)][64 d][hi|hi|lo over j]
                        const int kt = n >> 6, j = n & 63;
                        __nv_bfloat16* tb = V3o + ((size_t)(bh * 16 + kt) * 64) * 192;
                        __nv_bfloat16* r0p = tb + (size_t)d * 192;
                        __nv_bfloat16* r1p = r0p + 192;
                        r0p[j] = h0; r0p[64 + j] = h0; r0p[128 + j] = l0;
                        r1p[j] = h1; r1p[64 + j] = h1; r1p[128 + j] = l1;
                    }
                }
            }
        }
    }
}

// ---------------------------------------------------------------------------
// Tensor-core flash attention. grid (16 qtiles, 192 bh), 128 threads / 4 warps.
// ---------------------------------------------------------------------------
#define ATT_STRIDE 200       // elems per smem row (400 B)
#define ATT_TILE   (64 * ATT_STRIDE)
#define ATT_SMEM   (4 * ATT_TILE * 2)

__global__ __launch_bounds__(128) void fattn_kernel(
    const __nv_bfloat16* __restrict__ q3, const __nv_bfloat16* __restrict__ k3,
    const __nv_bfloat16* __restrict__ v3, __nv_bfloat16* __restrict__ out3)
{
    extern __shared__ __nv_bfloat16 sm[];
    __nv_bfloat16* Qs = sm;
    __nv_bfloat16* Ks = Qs + ATT_TILE;
    __nv_bfloat16* Vs = Ks + ATT_TILE;
    __nv_bfloat16* Ps = Vs + ATT_TILE;

    const int tid = threadIdx.x, wid = tid >> 5, lane = tid & 31;
    const int qt = blockIdx.x, bh = blockIdx.y;
    const int q0 = qt * 64;

    const uint32_t qs_u = smem_u32(Qs);
    const uint32_t ks_u = smem_u32(Ks);
    const uint32_t vs_u = smem_u32(Vs);

    {
        const __nv_bfloat16* gQ = q3 + ((size_t)bh * 1024 + q0) * 192;
#pragma unroll
        for (int i = 0; i < 12; i++) {
            const int e = tid + i * 128;
            const int rw = e / 24, cc = e % 24;
            cp16(qs_u + rw * 400 + cc * 16, gQ + rw * 192 + cc * 8);
        }
    }
    CP_COMMIT();

    const uint32_t lrow = lane & 15;
    const uint32_t lcolb = (lane >> 4) * 16;
    const uint32_t a_q = qs_u + (wid * 16 + lrow) * 400 + lcolb;
    const uint32_t a_p = smem_u32(Ps) + (wid * 16 + lrow) * 400 + lcolb;

    float mrun[2] = {-1e30f, -1e30f}, lrun[2] = {0.f, 0.f};
    float accO[8][4];
#pragma unroll
    for (int f = 0; f < 8; f++)
#pragma unroll
        for (int v = 0; v < 4; v++) accO[f][v] = 0.f;

    for (int kt = 0; kt < 16; kt++) {
        __syncthreads();
        {
            const __nv_bfloat16* gK = k3 + ((size_t)bh * 1024 + kt * 64) * 192;
            const __nv_bfloat16* gV = v3 + ((size_t)(bh * 16 + kt) * 64) * 192;
#pragma unroll
            for (int i = 0; i < 12; i++) {
                const int e = tid + i * 128;
                const int rw = e / 24, cc = e % 24;
                cp16(ks_u + rw * 400 + cc * 16, gK + rw * 192 + cc * 8);
                cp16(vs_u + rw * 400 + cc * 16, gV + rw * 192 + cc * 8);
            }
        }
        CP_COMMIT();
        CP_WAIT0();
        __syncthreads();

        float sacc[8][4];
#pragma unroll
        for (int f = 0; f < 8; f++)
#pragma unroll
            for (int v = 0; v < 4; v++) sacc[f][v] = 0.f;
#pragma unroll
        for (int ks = 0; ks < 12; ks++) {
            uint32_t af[4], bfr[4][4];
            ldsm4(af, a_q + ks * 32);
#pragma unroll
            for (int ni = 0; ni < 4; ni++)
                ldsm4(bfr[ni], ks_u + (ni * 16 + lrow) * 400 + lcolb + ks * 32);
#pragma unroll
            for (int ni = 0; ni < 4; ni++) {
                mma16816(sacc[2 * ni],     af, bfr[ni][0], bfr[ni][2]);
                mma16816(sacc[2 * ni + 1], af, bfr[ni][1], bfr[ni][3]);
            }
        }
#pragma unroll
        for (int f = 0; f < 8; f++)
#pragma unroll
            for (int v = 0; v < 4; v++) sacc[f][v] *= 0.125f;

#pragma unroll
        for (int hf = 0; hf < 2; hf++) {
            float mt = -1e30f;
#pragma unroll
            for (int f = 0; f < 8; f++)
                mt = fmaxf(mt, fmaxf(sacc[f][2 * hf], sacc[f][2 * hf + 1]));
            mt = fmaxf(mt, __shfl_xor_sync(0xffffffffu, mt, 1));
            mt = fmaxf(mt, __shfl_xor_sync(0xffffffffu, mt, 2));
            const float mnew = fmaxf(mrun[hf], mt);
            const float corr = exp2f((mrun[hf] - mnew) * 1.4426950408889634f);
            float rs = 0.f;
            const int prow = wid * 16 + (lane >> 2) + hf * 8;
            __nv_bfloat16* pb = Ps + prow * ATT_STRIDE + (lane & 3) * 2;
#pragma unroll
            for (int f = 0; f < 8; f++) {
                float p0 = exp2f((sacc[f][2 * hf]     - mnew) * 1.4426950408889634f);
                float p1 = exp2f((sacc[f][2 * hf + 1] - mnew) * 1.4426950408889634f);
                rs += p0 + p1;
                __nv_bfloat16 h0, l0, h1, l1;
                split2(p0, h0, l0); split2(p1, h1, l1);
                __nv_bfloat162 hp, lp;
                hp.x = h0; hp.y = h1; lp.x = l0; lp.y = l1;
                *(__nv_bfloat162*)(pb + f * 8)        = hp;
                *(__nv_bfloat162*)(pb + 64 + f * 8)   = lp;
                *(__nv_bfloat162*)(pb + 128 + f * 8)  = hp;
            }
            rs += __shfl_xor_sync(0xffffffffu, rs, 1);
            rs += __shfl_xor_sync(0xffffffffu, rs, 2);
            lrun[hf] = lrun[hf] * corr + rs;
            mrun[hf] = mnew;
#pragma unroll
            for (int f = 0; f < 8; f++) {
                accO[f][2 * hf]     *= corr;
                accO[f][2 * hf + 1] *= corr;
            }
        }
        __syncthreads();

#pragma unroll
        for (int ks = 0; ks < 12; ks++) {
            uint32_t af[4], bfr[4][4];
            ldsm4(af, a_p + ks * 32);
#pragma unroll
            for (int ni = 0; ni < 4; ni++)
                ldsm4(bfr[ni], vs_u + (ni * 16 + lrow) * 400 + lcolb + ks * 32);
#pragma unroll
            for (int ni = 0; ni < 4; ni++) {
                mma16816(accO[2 * ni],     af, bfr[ni][0], bfr[ni][2]);
                mma16816(accO[2 * ni + 1], af, bfr[ni][1], bfr[ni][3]);
            }
        }
    }

    const int b = bh / NHEAD, h = bh - b * NHEAD;
#pragma unroll
    for (int hf = 0; hf < 2; hf++) {
        const float inv = 1.0f / lrun[hf];
        const int t = b * 1024 + q0 + wid * 16 + (lane >> 2) + hf * 8;
        __nv_bfloat16* orow = out3 + (size_t)t * K3_D;
        const int cbase = h * 64 + (lane & 3) * 2;
#pragma unroll
        for (int f = 0; f < 8; f++) {
            const float v0 = accO[f][2 * hf] * inv;
            const float v1 = accO[f][2 * hf + 1] * inv;
            __nv_bfloat16 h0, l0, h1, l1;
            split2(v0, h0, l0); split2(v1, h1, l1);
            __nv_bfloat162 hp, lp;
            hp.x = h0; hp.y = h1; lp.x = l0; lp.y = l1;
            const int c = cbase + f * 8;
            *(__nv_bfloat162*)(orow + c)             = hp;
            *(__nv_bfloat162*)(orow + c + D_DIM)     = lp;
            *(__nv_bfloat162*)(orow + c + 2 * D_DIM) = hp;
        }
    }
}

// ---------------------------------------------------------------------------
// Launch
// ---------------------------------------------------------------------------
extern "C" void kernel_launch(void* const* d_in, const int* in_sizes, int n_in,
                              void* d_out, int out_size)
{
    const float* x      = (const float*)d_in[0];
    const float* qkv_w  = (const float*)d_in[1];
    const float* proj_w = (const float*)d_in[2];
    const float* proj_b = (const float*)d_in[3];
    const float* fc1_w  = (const float*)d_in[4];
    const float* fc1_b  = (const float*)d_in[5];
    const float* fc2_w  = (const float*)d_in[6];
    const float* fc2_b  = (const float*)d_in[7];
    const float* n1g    = (const float*)d_in[8];
    const float* n1b    = (const float*)d_in[9];
    const float* n2g    = (const float*)d_in[10];
    const float* n2b    = (const float*)d_in[11];
    float* out = (float*)d_out;

    void *pa3, *ph3, *pq3, *pk3, *pv3, *pwq, *pwp, *pw1, *pw2;
    cudaGetSymbolAddress(&pa3, g_a3);
    cudaGetSymbolAddress(&ph3, g_h3);
    cudaGetSymbolAddress(&pq3, g_q3);
    cudaGetSymbolAddress(&pk3, g_k3);
    cudaGetSymbolAddress(&pv3, g_v3);
    cudaGetSymbolAddress(&pwq, g_wqkv3);
    cudaGetSymbolAddress(&pwp, g_wproj3);
    cudaGetSymbolAddress(&pw1, g_wfc13);
    cudaGetSymbolAddress(&pw2, g_wfc23);
    __nv_bfloat16* a3  = (__nv_bfloat16*)pa3;
    __nv_bfloat16* h3  = (__nv_bfloat16*)ph3;
    __nv_bfloat16* q3  = (__nv_bfloat16*)pq3;
    __nv_bfloat16* k3  = (__nv_bfloat16*)pk3;
    __nv_bfloat16* v3  = (__nv_bfloat16*)pv3;
    __nv_bfloat16* wq3 = (__nv_bfloat16*)pwq;
    __nv_bfloat16* wp3 = (__nv_bfloat16*)pwp;
    __nv_bfloat16* w13 = (__nv_bfloat16*)pw1;
    __nv_bfloat16* w23 = (__nv_bfloat16*)pw2;

    cudaFuncSetAttribute(hgemm_kernel<1>, cudaFuncAttributeMaxDynamicSharedMemorySize, HG_SMEM);
    cudaFuncSetAttribute(hgemm_kernel<2>, cudaFuncAttributeMaxDynamicSharedMemorySize, HG_SMEM);
    cudaFuncSetAttribute(hgemm_kernel<3>, cudaFuncAttributeMaxDynamicSharedMemorySize, HG_SMEM);
    cudaFuncSetAttribute(fattn_kernel, cudaFuncAttributeMaxDynamicSharedMemorySize, ATT_SMEM);

    // 0) pack weights (hi|hi|lo along K)
    pack_w_kernel<<<(QKV_N * D_DIM + 255) / 256, 256>>>(qkv_w,  wq3, QKV_N * D_DIM,  D_DIM);
    pack_w_kernel<<<(D_DIM * D_DIM + 255) / 256, 256>>>(proj_w, wp3, D_DIM * D_DIM,  D_DIM);
    pack_w_kernel<<<(HID_DIM * D_DIM + 255) / 256, 256>>>(fc1_w, w13, HID_DIM * D_DIM, D_DIM);
    pack_w_kernel<<<(D_DIM * HID_DIM + 255) / 256, 256>>>(fc2_w, w23, D_DIM * HID_DIM, HID_DIM);

    // 1) LN1 + pack (hi|lo|hi)
    ln_pack_kernel<<<T_TOK, 256>>>(x, n1g, n1b, a3);
    // 2) QKV GEMM -> split-packed Q3/K3/V3 attention operands
    hgemm_kernel<1><<<dim3(QKV_N / 256, T_TOK / 128), 512, HG_SMEM>>>(
        a3, wq3, nullptr, nullptr, nullptr, nullptr, q3, k3, v3, K3_D, QKV_N);
    // 3) tensor-core flash attention -> packed a3
    fattn_kernel<<<dim3(16, BH), 128, ATT_SMEM>>>(q3, k3, v3, a3);
    // 4) x1 = x + attn @ proj_w^T + proj_b -> d_out
    hgemm_kernel<3><<<dim3(D_DIM / 256, T_TOK / 128), 512, HG_SMEM>>>(
        a3, wp3, proj_b, x, out, nullptr, nullptr, nullptr, nullptr, K3_D, D_DIM);
    // 5) LN2 + pack
    ln_pack_kernel<<<T_TOK, 256>>>(out, n2g, n2b, a3);
    // 6) h3 = pack(gelu(ln2 @ fc1_w^T + fc1_b))
    hgemm_kernel<2><<<dim3(HID_DIM / 256, T_TOK / 128), 512, HG_SMEM>>>(
        a3, w13, fc1_b, nullptr, nullptr, h3, nullptr, nullptr, nullptr, K3_D, HID_DIM);
    // 7) out = x1 + h @ fc2_w^T + fc2_b (in-place residual)
    hgemm_kernel<3><<<dim3(D_DIM / 256, T_TOK / 128), 512, HG_SMEM>>>(
        h3, w23, fc2_b, out, out, nullptr, nullptr, nullptr, nullptr, K3_H, D_DIM);
}

// round 16
// speedup vs baseline: 1.5839x; 1.3111x over previous
#include <cuda_runtime.h>
#include <cuda_bf16.h>
#include <cuda_fp16.h>
#include <math.h>
#include <stdint.h>

// ---------------------------------------------------------------------------
// Problem constants
// ---------------------------------------------------------------------------
#define T_TOK 16384          // B*N tokens
#define D_DIM 768
#define HID_DIM 3072
#define NHEAD 12
#define QKV_N 2304
#define K2_D 1536            // 2*768   fp16 [hi|lo] packed K
#define K2_H 6144            // 2*3072
#define K3_D 2304            // bf16 attn-operand packing (row len for a3-era layouts)
#define BH   192             // B*H

// ---------------------------------------------------------------------------
// Scratch (device globals; allocation-free per harness rules)
// ---------------------------------------------------------------------------
__device__ __align__(256) __half        g_a2  [(size_t)T_TOK * K2_D];    //  48 MB activations [hi|lo]
__device__ __align__(256) __half        g_h2  [(size_t)T_TOK * K2_H];    // 192 MB gelu(fc1) [hi|lo]
__device__ __align__(256) __nv_bfloat16 g_q3  [(size_t)BH * 1024 * 192];
__device__ __align__(256) __nv_bfloat16 g_k3  [(size_t)BH * 1024 * 192];
__device__ __align__(256) __nv_bfloat16 g_v3  [(size_t)BH * 16 * 64 * 192];
__device__ __align__(256) __half g_wqkv2 [(size_t)QKV_N  * K2_D];
__device__ __align__(256) __half g_wproj2[(size_t)D_DIM  * K2_D];
__device__ __align__(256) __half g_wfc12 [(size_t)HID_DIM* K2_D];
__device__ __align__(256) __half g_wfc22 [(size_t)D_DIM  * K2_H];

// ---------------------------------------------------------------------------
// PTX helpers (portable: cp.async / ldmatrix / mma.sync)
// ---------------------------------------------------------------------------
__device__ __forceinline__ uint32_t smem_u32(const void* p) {
    uint32_t a;
    asm("{ .reg .u64 t; cvta.to.shared.u64 t, %1; cvt.u32.u64 %0, t; }" : "=r"(a) : "l"(p));
    return a;
}

__device__ __forceinline__ void cp16(uint32_t saddr, const void* gaddr) {
    asm volatile("cp.async.cg.shared.global [%0], [%1], 16;" :: "r"(saddr), "l"(gaddr));
}
#define CP_COMMIT() asm volatile("cp.async.commit_group;" ::: "memory")
#define CP_WAIT1()  asm volatile("cp.async.wait_group 1;" ::: "memory")
#define CP_WAIT0()  asm volatile("cp.async.wait_group 0;" ::: "memory")

__device__ __forceinline__ void ldsm4(uint32_t* r, uint32_t addr) {
    asm volatile("ldmatrix.sync.aligned.m8n8.x4.shared.b16 {%0,%1,%2,%3}, [%4];"
                 : "=r"(r[0]), "=r"(r[1]), "=r"(r[2]), "=r"(r[3]) : "r"(addr));
}

// fp16 MMA (weight GEMMs)
__device__ __forceinline__ void mma16816h(float* c, const uint32_t* a,
                                          uint32_t b0, uint32_t b1) {
    asm volatile(
        "mma.sync.aligned.m16n8k16.row.col.f32.f16.f16.f32 "
        "{%0,%1,%2,%3}, {%4,%5,%6,%7}, {%8,%9}, {%0,%1,%2,%3};"
        : "+f"(c[0]), "+f"(c[1]), "+f"(c[2]), "+f"(c[3])
        : "r"(a[0]), "r"(a[1]), "r"(a[2]), "r"(a[3]), "r"(b0), "r"(b1));
}
// bf16 MMA (attention)
__device__ __forceinline__ void mma16816b(float* c, const uint32_t* a,
                                          uint32_t b0, uint32_t b1) {
    asm volatile(
        "mma.sync.aligned.m16n8k16.row.col.f32.bf16.bf16.f32 "
        "{%0,%1,%2,%3}, {%4,%5,%6,%7}, {%8,%9}, {%0,%1,%2,%3};"
        : "+f"(c[0]), "+f"(c[1]), "+f"(c[2]), "+f"(c[3])
        : "r"(a[0]), "r"(a[1]), "r"(a[2]), "r"(a[3]), "r"(b0), "r"(b1));
}

__device__ __forceinline__ void split2b(float x, __nv_bfloat16& hi, __nv_bfloat16& lo) {
    hi = __float2bfloat16(x);
    lo = __float2bfloat16(x - __bfloat162float(hi));
}
__device__ __forceinline__ void split2h(float x, __half& hi, __half& lo) {
    hi = __float2half(x);
    lo = __float2half(x - __half2float(hi));
}

// ---------------------------------------------------------------------------
// Weight pack: W[N,K] fp32 -> W2[N,2K] fp16 as [hi | hi]
// ---------------------------------------------------------------------------
__global__ __launch_bounds__(256) void pack_w_kernel(
    const float* __restrict__ W, __half* __restrict__ W2, int NK, int K)
{
    int idx = blockIdx.x * 256 + threadIdx.x;
    if (idx >= NK) return;
    int n = idx / K, k = idx - n * K;
    __half hi = __float2half(W[idx]);
    size_t base = (size_t)n * 2 * K + k;
    W2[base] = hi; W2[base + K] = hi;
}

// ---------------------------------------------------------------------------
// Fused LayerNorm + activation pack: out2[t, 2*768] = [hi | lo] fp16
// ---------------------------------------------------------------------------
__global__ __launch_bounds__(256) void ln_pack_kernel(
    const float* __restrict__ x, const float* __restrict__ gam,
    const float* __restrict__ bet, __half* __restrict__ out2)
{
    const int row = blockIdx.x;
    const int tid = threadIdx.x;
    const float* xr = x + (size_t)row * D_DIM;
    float v0 = xr[tid], v1 = xr[tid + 256], v2 = xr[tid + 512];
    float s = v0 + v1 + v2;
    float q = v0 * v0 + v1 * v1 + v2 * v2;

    __shared__ float sred[8], qred[8];
#pragma unroll
    for (int o = 16; o > 0; o >>= 1) {
        s += __shfl_xor_sync(0xffffffffu, s, o);
        q += __shfl_xor_sync(0xffffffffu, q, o);
    }
    if ((tid & 31) == 0) { sred[tid >> 5] = s; qred[tid >> 5] = q; }
    __syncthreads();
    s = 0.f; q = 0.f;
#pragma unroll
    for (int i = 0; i < 8; i++) { s += sred[i]; q += qred[i]; }
    const float mean = s * (1.0f / 768.0f);
    const float var  = q * (1.0f / 768.0f) - mean * mean;
    const float rstd = rsqrtf(var + 1e-6f);

    __half* orow = out2 + (size_t)row * K2_D;
#pragma unroll
    for (int e = 0; e < 3; e++) {
        const int c = tid + e * 256;
        const float v = (e == 0 ? v0 : (e == 1 ? v1 : v2));
        const float y = (v - mean) * rstd * gam[c] + bet[c];
        __half hi, lo;
        split2h(y, hi, lo);
        orow[c] = hi; orow[c + D_DIM] = lo;
    }
}

// ---------------------------------------------------------------------------
// HMMA GEMM (NT) fp16: C[M,Nf] = A2[M,K2] * B2[Nf,K2]^T  (fp32 accum)
// CTA 128x256, BK=32, 512 threads / 16 warps as 4(m)x4(n), warp tile 32x64,
// 3-stage cp.async pipeline, ONE __syncthreads per iter.
// EPI: 1 = qkv split-pack (bf16) into Q3/K3/V3; 2 = bias+GELU -> fp16 [hi|lo];
//      3 = bias + residual -> fp32
// ---------------------------------------------------------------------------
#define STG_A_BYTES (128 * 80)            // 10240
#define STG_BYTES   (128 * 80 + 256 * 80) // 30720
#define NSTAGE 3
#define HG_SMEM (NSTAGE * STG_BYTES)      // 92160

template <int EPI>
__global__ __launch_bounds__(512) void hgemm_kernel(
    const __half* __restrict__ A2, const __half* __restrict__ B2,
    const float* __restrict__ bias, const float* __restrict__ resid,
    float* __restrict__ Cf, __half* __restrict__ Cp,
    __nv_bfloat16* __restrict__ Q3o, __nv_bfloat16* __restrict__ K3o,
    __nv_bfloat16* __restrict__ V3o,
    int K2, int ldN)
{
    extern __shared__ __align__(128) char smraw[];
    const uint32_t su = smem_u32(smraw);

    const int tid  = threadIdx.x;
    const int wid  = tid >> 5;
    const int lane = tid & 31;
    const int wm   = wid >> 2;          // 0..3  (32-row slice)
    const int wn   = wid & 3;           // 0..3  (64-col slice)

    const int m0 = blockIdx.y * 128;
    const int n0 = blockIdx.x * 256;

    // A: 4 threads per row (16B each); B: 2 threads per row (32B each)
    const int arow = tid >> 2, aq = tid & 3;
    const int brow = tid >> 1, bhalf = tid & 1;
    const __half* ga = A2 + (size_t)(m0 + arow) * K2 + aq * 8;
    const __half* gb = B2 + (size_t)(n0 + brow) * K2 + bhalf * 16;
    const uint32_t a_st = arow * 80 + aq * 16;
    const uint32_t b_st = STG_A_BYTES + brow * 80 + bhalf * 32;

    const uint32_t lrow  = lane & 15;
    const uint32_t lcolb = (lane >> 4) * 16;
    const uint32_t a_ld  = (wm * 32 + lrow) * 80 + lcolb;
    const uint32_t b_ld  = STG_A_BYTES + (wn * 64 + lrow) * 80 + lcolb;

    float acc[2][8][4];
#pragma unroll
    for (int i = 0; i < 2; i++)
#pragma unroll
        for (int j = 0; j < 8; j++)
#pragma unroll
            for (int v = 0; v < 4; v++) acc[i][j][v] = 0.f;

    const int Tn = K2 / 32;

    // Prologue: stages 0..1
#pragma unroll
    for (int s = 0; s < NSTAGE - 1; s++) {
        const uint32_t sb = su + s * STG_BYTES;
        cp16(sb + a_st, ga + s * 32);
        cp16(sb + b_st,      gb + s * 32);
        cp16(sb + b_st + 16, gb + s * 32 + 8);
        CP_COMMIT();
    }

    int stg_idx = 0;
    for (int t = 0; t < Tn; t++) {
        CP_WAIT1();
        __syncthreads();

        const uint32_t stg = su + stg_idx * STG_BYTES;
        const uint32_t abase = stg + a_ld;
        const uint32_t bbase = stg + b_ld;
#pragma unroll
        for (int ks = 0; ks < 2; ks++) {
            uint32_t af[2][4], bfr[4][4];
            ldsm4(af[0], abase + ks * 32);
            ldsm4(af[1], abase + 16 * 80 + ks * 32);
#pragma unroll
            for (int ni = 0; ni < 4; ni++)
                ldsm4(bfr[ni], bbase + ni * 16 * 80 + ks * 32);
#pragma unroll
            for (int mi = 0; mi < 2; mi++)
#pragma unroll
                for (int ni = 0; ni < 4; ni++) {
                    mma16816h(acc[mi][2 * ni],     af[mi], bfr[ni][0], bfr[ni][2]);
                    mma16816h(acc[mi][2 * ni + 1], af[mi], bfr[ni][1], bfr[ni][3]);
                }
        }

        // Prefetch stage t+2 into the buffer consumed at iter t-1.
        const int tp = t + NSTAGE - 1;
        if (tp < Tn) {
            int pidx = stg_idx + (NSTAGE - 1);
            if (pidx >= NSTAGE) pidx -= NSTAGE;
            const uint32_t sb = su + pidx * STG_BYTES;
            cp16(sb + a_st, ga + tp * 32);
            cp16(sb + b_st,      gb + tp * 32);
            cp16(sb + b_st + 16, gb + tp * 32 + 8);
        }
        CP_COMMIT();   // empty group at tail keeps wait_group bookkeeping exact

        if (++stg_idx == NSTAGE) stg_idx = 0;
    }

    // -------------------- Epilogue --------------------
    const int lm = lane >> 2;
    const int lc = (lane & 3) * 2;

#pragma unroll
    for (int mi = 0; mi < 2; mi++) {
#pragma unroll
        for (int nj = 0; nj < 8; nj++) {
            const int row = m0 + wm * 32 + mi * 16 + lm;
            const int col = n0 + wn * 64 + nj * 8 + lc;
            const float* c = acc[mi][nj];
#pragma unroll
            for (int h = 0; h < 2; h++) {
                const int r = row + h * 8;
                float v0 = c[2 * h], v1 = c[2 * h + 1];
                if (EPI == 3) {
                    const float2 rr = *(const float2*)(resid + (size_t)r * ldN + col);
                    float2 o;
                    o.x = v0 + bias[col]     + rr.x;
                    o.y = v1 + bias[col + 1] + rr.y;
                    *(float2*)(Cf + (size_t)r * ldN + col) = o;
                } else if (EPI == 2) {  // bias + exact GELU -> fp16 [hi|lo]
                    v0 += bias[col];
                    v1 += bias[col + 1];
                    v0 = 0.5f * v0 * (1.0f + erff(v0 * 0.70710678118654752f));
                    v1 = 0.5f * v1 * (1.0f + erff(v1 * 0.70710678118654752f));
                    __half h0, l0, h1, l1;
                    split2h(v0, h0, l0); split2h(v1, h1, l1);
                    __half2 hh, ll;
                    hh.x = h0; hh.y = h1; ll.x = l0; ll.y = l1;
                    __half* rb = Cp + (size_t)r * (2 * (size_t)ldN);
                    *(__half2*)(rb + col)       = hh;
                    *(__half2*)(rb + ldN + col) = ll;
                } else {  // EPI == 1: split-pack Q/K/V attention operands (bf16)
                    const int b  = r >> 10, n = r & 1023;
                    const int which = col / 768;
                    const int rem = col - which * 768;
                    const int hh_ = rem >> 6, d = rem & 63;
                    const int bh = b * NHEAD + hh_;
                    __nv_bfloat16 h0, l0, h1, l1;
                    split2b(v0, h0, l0); split2b(v1, h1, l1);
                    __nv_bfloat162 hp, lp;
                    hp.x = h0; hp.y = h1; lp.x = l0; lp.y = l1;
                    if (which == 0) {          // Q: [hi | lo | hi]
                        __nv_bfloat16* base = Q3o + ((size_t)bh * 1024 + n) * 192;
                        *(__nv_bfloat162*)(base + d)       = hp;
                        *(__nv_bfloat162*)(base + 64 + d)  = lp;
                        *(__nv_bfloat162*)(base + 128 + d) = hp;
                    } else if (which == 1) {   // K: [hi | hi | lo]
                        __nv_bfloat16* base = K3o + ((size_t)bh * 1024 + n) * 192;
                        *(__nv_bfloat162*)(base + d)       = hp;
                        *(__nv_bfloat162*)(base + 64 + d)  = hp;
                        *(__nv_bfloat162*)(base + 128 + d) = lp;
                    } else {                   // V tile [(bh,kt)][64 d][hi|hi|lo over j]
                        const int kt = n >> 6, j = n & 63;
                        __nv_bfloat16* tb = V3o + ((size_t)(bh * 16 + kt) * 64) * 192;
                        __nv_bfloat16* r0p = tb + (size_t)d * 192;
                        __nv_bfloat16* r1p = r0p + 192;
                        r0p[j] = h0; r0p[64 + j] = h0; r0p[128 + j] = l0;
                        r1p[j] = h1; r1p[64 + j] = h1; r1p[128 + j] = l1;
                    }
                }
            }
        }
    }
}

// ---------------------------------------------------------------------------
// Tensor-core flash attention (bf16 3-term, unchanged numerics).
// grid (16 qtiles, 192 bh), 128 threads / 4 warps.
// Output now packs fp16 [hi|lo] into a2 for the fp16 proj GEMM.
// ---------------------------------------------------------------------------
#define ATT_STRIDE 200       // elems per smem row (400 B)
#define ATT_TILE   (64 * ATT_STRIDE)
#define ATT_SMEM   (4 * ATT_TILE * 2)

__global__ __launch_bounds__(128) void fattn_kernel(
    const __nv_bfloat16* __restrict__ q3, const __nv_bfloat16* __restrict__ k3,
    const __nv_bfloat16* __restrict__ v3, __half* __restrict__ out2)
{
    extern __shared__ __nv_bfloat16 sm[];
    __nv_bfloat16* Qs = sm;
    __nv_bfloat16* Ks = Qs + ATT_TILE;
    __nv_bfloat16* Vs = Ks + ATT_TILE;
    __nv_bfloat16* Ps = Vs + ATT_TILE;

    const int tid = threadIdx.x, wid = tid >> 5, lane = tid & 31;
    const int qt = blockIdx.x, bh = blockIdx.y;
    const int q0 = qt * 64;

    const uint32_t qs_u = smem_u32(Qs);
    const uint32_t ks_u = smem_u32(Ks);
    const uint32_t vs_u = smem_u32(Vs);

    {
        const __nv_bfloat16* gQ = q3 + ((size_t)bh * 1024 + q0) * 192;
#pragma unroll
        for (int i = 0; i < 12; i++) {
            const int e = tid + i * 128;
            const int rw = e / 24, cc = e % 24;
            cp16(qs_u + rw * 400 + cc * 16, gQ + rw * 192 + cc * 8);
        }
    }
    CP_COMMIT();

    const uint32_t lrow = lane & 15;
    const uint32_t lcolb = (lane >> 4) * 16;
    const uint32_t a_q = qs_u + (wid * 16 + lrow) * 400 + lcolb;
    const uint32_t a_p = smem_u32(Ps) + (wid * 16 + lrow) * 400 + lcolb;

    float mrun[2] = {-1e30f, -1e30f}, lrun[2] = {0.f, 0.f};
    float accO[8][4];
#pragma unroll
    for (int f = 0; f < 8; f++)
#pragma unroll
        for (int v = 0; v < 4; v++) accO[f][v] = 0.f;

    for (int kt = 0; kt < 16; kt++) {
        __syncthreads();
        {
            const __nv_bfloat16* gK = k3 + ((size_t)bh * 1024 + kt * 64) * 192;
            const __nv_bfloat16* gV = v3 + ((size_t)(bh * 16 + kt) * 64) * 192;
#pragma unroll
            for (int i = 0; i < 12; i++) {
                const int e = tid + i * 128;
                const int rw = e / 24, cc = e % 24;
                cp16(ks_u + rw * 400 + cc * 16, gK + rw * 192 + cc * 8);
                cp16(vs_u + rw * 400 + cc * 16, gV + rw * 192 + cc * 8);
            }
        }
        CP_COMMIT();
        CP_WAIT0();
        __syncthreads();

        float sacc[8][4];
#pragma unroll
        for (int f = 0; f < 8; f++)
#pragma unroll
            for (int v = 0; v < 4; v++) sacc[f][v] = 0.f;
#pragma unroll
        for (int ks = 0; ks < 12; ks++) {
            uint32_t af[4], bfr[4][4];
            ldsm4(af, a_q + ks * 32);
#pragma unroll
            for (int ni = 0; ni < 4; ni++)
                ldsm4(bfr[ni], ks_u + (ni * 16 + lrow) * 400 + lcolb + ks * 32);
#pragma unroll
            for (int ni = 0; ni < 4; ni++) {
                mma16816b(sacc[2 * ni],     af, bfr[ni][0], bfr[ni][2]);
                mma16816b(sacc[2 * ni + 1], af, bfr[ni][1], bfr[ni][3]);
            }
        }
#pragma unroll
        for (int f = 0; f < 8; f++)
#pragma unroll
            for (int v = 0; v < 4; v++) sacc[f][v] *= 0.125f;

#pragma unroll
        for (int hf = 0; hf < 2; hf++) {
            float mt = -1e30f;
#pragma unroll
            for (int f = 0; f < 8; f++)
                mt = fmaxf(mt, fmaxf(sacc[f][2 * hf], sacc[f][2 * hf + 1]));
            mt = fmaxf(mt, __shfl_xor_sync(0xffffffffu, mt, 1));
            mt = fmaxf(mt, __shfl_xor_sync(0xffffffffu, mt, 2));
            const float mnew = fmaxf(mrun[hf], mt);
            const float corr = exp2f((mrun[hf] - mnew) * 1.4426950408889634f);
            float rs = 0.f;
            const int prow = wid * 16 + (lane >> 2) + hf * 8;
            __nv_bfloat16* pb = Ps + prow * ATT_STRIDE + (lane & 3) * 2;
#pragma unroll
            for (int f = 0; f < 8; f++) {
                float p0 = exp2f((sacc[f][2 * hf]     - mnew) * 1.4426950408889634f);
                float p1 = exp2f((sacc[f][2 * hf + 1] - mnew) * 1.4426950408889634f);
                rs += p0 + p1;
                __nv_bfloat16 h0, l0, h1, l1;
                split2b(p0, h0, l0); split2b(p1, h1, l1);
                __nv_bfloat162 hp, lp;
                hp.x = h0; hp.y = h1; lp.x = l0; lp.y = l1;
                *(__nv_bfloat162*)(pb + f * 8)        = hp;
                *(__nv_bfloat162*)(pb + 64 + f * 8)   = lp;
                *(__nv_bfloat162*)(pb + 128 + f * 8)  = hp;
            }
            rs += __shfl_xor_sync(0xffffffffu, rs, 1);
            rs += __shfl_xor_sync(0xffffffffu, rs, 2);
            lrun[hf] = lrun[hf] * corr + rs;
            mrun[hf] = mnew;
#pragma unroll
            for (int f = 0; f < 8; f++) {
                accO[f][2 * hf]     *= corr;
                accO[f][2 * hf + 1] *= corr;
            }
        }
        __syncthreads();

#pragma unroll
        for (int ks = 0; ks < 12; ks++) {
            uint32_t af[4], bfr[4][4];
            ldsm4(af, a_p + ks * 32);
#pragma unroll
            for (int ni = 0; ni < 4; ni++)
                ldsm4(bfr[ni], vs_u + (ni * 16 + lrow) * 400 + lcolb + ks * 32);
#pragma unroll
            for (int ni = 0; ni < 4; ni++) {
                mma16816b(accO[2 * ni],     af, bfr[ni][0], bfr[ni][2]);
                mma16816b(accO[2 * ni + 1], af, bfr[ni][1], bfr[ni][3]);
            }
        }
    }

    // Output: fp16 [hi|lo], row length 1536, for the fp16 proj GEMM
    const int b = bh / NHEAD, h = bh - b * NHEAD;
#pragma unroll
    for (int hf = 0; hf < 2; hf++) {
        const float inv = 1.0f / lrun[hf];
        const int t = b * 1024 + q0 + wid * 16 + (lane >> 2) + hf * 8;
        __half* orow = out2 + (size_t)t * K2_D;
        const int cbase = h * 64 + (lane & 3) * 2;
#pragma unroll
        for (int f = 0; f < 8; f++) {
            const float v0 = accO[f][2 * hf] * inv;
            const float v1 = accO[f][2 * hf + 1] * inv;
            __half h0, l0, h1, l1;
            split2h(v0, h0, l0); split2h(v1, h1, l1);
            __half2 hp, lp;
            hp.x = h0; hp.y = h1; lp.x = l0; lp.y = l1;
            const int c = cbase + f * 8;
            *(__half2*)(orow + c)         = hp;
            *(__half2*)(orow + c + D_DIM) = lp;
        }
    }
}

// ---------------------------------------------------------------------------
// Launch
// ---------------------------------------------------------------------------
extern "C" void kernel_launch(void* const* d_in, const int* in_sizes, int n_in,
                              void* d_out, int out_size)
{
    const float* x      = (const float*)d_in[0];
    const float* qkv_w  = (const float*)d_in[1];
    const float* proj_w = (const float*)d_in[2];
    const float* proj_b = (const float*)d_in[3];
    const float* fc1_w  = (const float*)d_in[4];
    const float* fc1_b  = (const float*)d_in[5];
    const float* fc2_w  = (const float*)d_in[6];
    const float* fc2_b  = (const float*)d_in[7];
    const float* n1g    = (const float*)d_in[8];
    const float* n1b    = (const float*)d_in[9];
    const float* n2g    = (const float*)d_in[10];
    const float* n2b    = (const float*)d_in[11];
    float* out = (float*)d_out;

    void *pa2, *ph2, *pq3, *pk3, *pv3, *pwq, *pwp, *pw1, *pw2;
    cudaGetSymbolAddress(&pa2, g_a2);
    cudaGetSymbolAddress(&ph2, g_h2);
    cudaGetSymbolAddress(&pq3, g_q3);
    cudaGetSymbolAddress(&pk3, g_k3);
    cudaGetSymbolAddress(&pv3, g_v3);
    cudaGetSymbolAddress(&pwq, g_wqkv2);
    cudaGetSymbolAddress(&pwp, g_wproj2);
    cudaGetSymbolAddress(&pw1, g_wfc12);
    cudaGetSymbolAddress(&pw2, g_wfc22);
    __half*        a2  = (__half*)pa2;
    __half*        h2  = (__half*)ph2;
    __nv_bfloat16* q3  = (__nv_bfloat16*)pq3;
    __nv_bfloat16* k3  = (__nv_bfloat16*)pk3;
    __nv_bfloat16* v3  = (__nv_bfloat16*)pv3;
    __half*        wq2 = (__half*)pwq;
    __half*        wp2 = (__half*)pwp;
    __half*        w12 = (__half*)pw1;
    __half*        w22 = (__half*)pw2;

    cudaFuncSetAttribute(hgemm_kernel<1>, cudaFuncAttributeMaxDynamicSharedMemorySize, HG_SMEM);
    cudaFuncSetAttribute(hgemm_kernel<2>, cudaFuncAttributeMaxDynamicSharedMemorySize, HG_SMEM);
    cudaFuncSetAttribute(hgemm_kernel<3>, cudaFuncAttributeMaxDynamicSharedMemorySize, HG_SMEM);
    cudaFuncSetAttribute(fattn_kernel, cudaFuncAttributeMaxDynamicSharedMemorySize, ATT_SMEM);

    // 0) pack weights (fp16 [hi|hi] along K)
    pack_w_kernel<<<(QKV_N * D_DIM + 255) / 256, 256>>>(qkv_w,  wq2, QKV_N * D_DIM,  D_DIM);
    pack_w_kernel<<<(D_DIM * D_DIM + 255) / 256, 256>>>(proj_w, wp2, D_DIM * D_DIM,  D_DIM);
    pack_w_kernel<<<(HID_DIM * D_DIM + 255) / 256, 256>>>(fc1_w, w12, HID_DIM * D_DIM, D_DIM);
    pack_w_kernel<<<(D_DIM * HID_DIM + 255) / 256, 256>>>(fc2_w, w22, D_DIM * HID_DIM, HID_DIM);

    // 1) LN1 + fp16 pack [hi|lo]
    ln_pack_kernel<<<T_TOK, 256>>>(x, n1g, n1b, a2);
    // 2) QKV GEMM (fp16) -> bf16 split-packed Q3/K3/V3 attention operands
    hgemm_kernel<1><<<dim3(QKV_N / 256, T_TOK / 128), 512, HG_SMEM>>>(
        a2, wq2, nullptr, nullptr, nullptr, nullptr, q3, k3, v3, K2_D, QKV_N);
    // 3) tensor-core flash attention (bf16 3-term) -> fp16 packed a2
    fattn_kernel<<<dim3(16, BH), 128, ATT_SMEM>>>(q3, k3, v3, a2);
    // 4) x1 = x + attn @ proj_w^T + proj_b -> d_out
    hgemm_kernel<3><<<dim3(D_DIM / 256, T_TOK / 128), 512, HG_SMEM>>>(
        a2, wp2, proj_b, x, out, nullptr, nullptr, nullptr, nullptr, K2_D, D_DIM);
    // 5) LN2 + fp16 pack
    ln_pack_kernel<<<T_TOK, 256>>>(out, n2g, n2b, a2);
    // 6) h2 = fp16-pack(gelu(ln2 @ fc1_w^T + fc1_b))
    hgemm_kernel<2><<<dim3(HID_DIM / 256, T_TOK / 128), 512, HG_SMEM>>>(
        a2, w12, fc1_b, nullptr, nullptr, h2, nullptr, nullptr, nullptr, K2_D, HID_DIM);
    // 7) out = x1 + h @ fc2_w^T + fc2_b (in-place residual)
    hgemm_kernel<3><<<dim3(D_DIM / 256, T_TOK / 128), 512, HG_SMEM>>>(
        h2, w22, fc2_b, out, out, nullptr, nullptr, nullptr, nullptr, K2_H, D_DIM);
}

// round 17
// speedup vs baseline: 1.7956x; 1.1336x over previous
#include <cuda_runtime.h>
#include <cuda_bf16.h>
#include <cuda_fp16.h>
#include <math.h>
#include <stdint.h>

// ---------------------------------------------------------------------------
// Problem constants
// ---------------------------------------------------------------------------
#define T_TOK 16384          // B*N tokens
#define D_DIM 768
#define HID_DIM 3072
#define NHEAD 12
#define QKV_N 2304
#define K2_D 1536            // 2*768   fp16 [hi|lo] packed K
#define K2_H 6144            // 2*3072
#define KA   128             // attention packed K (2*64)
#define BH   192             // B*H

// ---------------------------------------------------------------------------
// Scratch (device globals; allocation-free per harness rules)
// ---------------------------------------------------------------------------
__device__ __align__(256) __half g_a2  [(size_t)T_TOK * K2_D];    //  48 MB activations [hi|lo]
__device__ __align__(256) __half g_h2  [(size_t)T_TOK * K2_H];    // 192 MB gelu(fc1) [hi|lo]
__device__ __align__(256) __half g_q2  [(size_t)BH * 1024 * KA];  // 50 MB
__device__ __align__(256) __half g_k2  [(size_t)BH * 1024 * KA];  // 50 MB
__device__ __align__(256) __half g_v2  [(size_t)BH * 16 * 64 * KA]; // 50 MB
__device__ __align__(256) __half g_wqkv2 [(size_t)QKV_N  * K2_D];
__device__ __align__(256) __half g_wproj2[(size_t)D_DIM  * K2_D];
__device__ __align__(256) __half g_wfc12 [(size_t)HID_DIM* K2_D];
__device__ __align__(256) __half g_wfc22 [(size_t)D_DIM  * K2_H];

// ---------------------------------------------------------------------------
// PTX helpers (portable: cp.async / ldmatrix / mma.sync)
// ---------------------------------------------------------------------------
__device__ __forceinline__ uint32_t smem_u32(const void* p) {
    uint32_t a;
    asm("{ .reg .u64 t; cvta.to.shared.u64 t, %1; cvt.u32.u64 %0, t; }" : "=r"(a) : "l"(p));
    return a;
}

__device__ __forceinline__ void cp16(uint32_t saddr, const void* gaddr) {
    asm volatile("cp.async.cg.shared.global [%0], [%1], 16;" :: "r"(saddr), "l"(gaddr));
}
#define CP_COMMIT() asm volatile("cp.async.commit_group;" ::: "memory")
#define CP_WAIT1()  asm volatile("cp.async.wait_group 1;" ::: "memory")
#define CP_WAIT0()  asm volatile("cp.async.wait_group 0;" ::: "memory")

__device__ __forceinline__ void ldsm4(uint32_t* r, uint32_t addr) {
    asm volatile("ldmatrix.sync.aligned.m8n8.x4.shared.b16 {%0,%1,%2,%3}, [%4];"
                 : "=r"(r[0]), "=r"(r[1]), "=r"(r[2]), "=r"(r[3]) : "r"(addr));
}

// fp16 MMA
__device__ __forceinline__ void mma16816h(float* c, const uint32_t* a,
                                          uint32_t b0, uint32_t b1) {
    asm volatile(
        "mma.sync.aligned.m16n8k16.row.col.f32.f16.f16.f32 "
        "{%0,%1,%2,%3}, {%4,%5,%6,%7}, {%8,%9}, {%0,%1,%2,%3};"
        : "+f"(c[0]), "+f"(c[1]), "+f"(c[2]), "+f"(c[3])
        : "r"(a[0]), "r"(a[1]), "r"(a[2]), "r"(a[3]), "r"(b0), "r"(b1));
}

__device__ __forceinline__ void split2h(float x, __half& hi, __half& lo) {
    hi = __float2half(x);
    lo = __float2half(x - __half2float(hi));
}

// ---------------------------------------------------------------------------
// Weight pack: W[N,K] fp32 -> W2[N,2K] fp16 as [hi | hi]
// ---------------------------------------------------------------------------
__global__ __launch_bounds__(256) void pack_w_kernel(
    const float* __restrict__ W, __half* __restrict__ W2, int NK, int K)
{
    int idx = blockIdx.x * 256 + threadIdx.x;
    if (idx >= NK) return;
    int n = idx / K, k = idx - n * K;
    __half hi = __float2half(W[idx]);
    size_t base = (size_t)n * 2 * K + k;
    W2[base] = hi; W2[base + K] = hi;
}

// ---------------------------------------------------------------------------
// Fused LayerNorm + activation pack: out2[t, 2*768] = [hi | lo] fp16
// ---------------------------------------------------------------------------
__global__ __launch_bounds__(256) void ln_pack_kernel(
    const float* __restrict__ x, const float* __restrict__ gam,
    const float* __restrict__ bet, __half* __restrict__ out2)
{
    const int row = blockIdx.x;
    const int tid = threadIdx.x;
    const float* xr = x + (size_t)row * D_DIM;
    float v0 = xr[tid], v1 = xr[tid + 256], v2 = xr[tid + 512];
    float s = v0 + v1 + v2;
    float q = v0 * v0 + v1 * v1 + v2 * v2;

    __shared__ float sred[8], qred[8];
#pragma unroll
    for (int o = 16; o > 0; o >>= 1) {
        s += __shfl_xor_sync(0xffffffffu, s, o);
        q += __shfl_xor_sync(0xffffffffu, q, o);
    }
    if ((tid & 31) == 0) { sred[tid >> 5] = s; qred[tid >> 5] = q; }
    __syncthreads();
    s = 0.f; q = 0.f;
#pragma unroll
    for (int i = 0; i < 8; i++) { s += sred[i]; q += qred[i]; }
    const float mean = s * (1.0f / 768.0f);
    const float var  = q * (1.0f / 768.0f) - mean * mean;
    const float rstd = rsqrtf(var + 1e-6f);

    __half* orow = out2 + (size_t)row * K2_D;
#pragma unroll
    for (int e = 0; e < 3; e++) {
        const int c = tid + e * 256;
        const float v = (e == 0 ? v0 : (e == 1 ? v1 : v2));
        const float y = (v - mean) * rstd * gam[c] + bet[c];
        __half hi, lo;
        split2h(y, hi, lo);
        orow[c] = hi; orow[c + D_DIM] = lo;
    }
}

// ---------------------------------------------------------------------------
// HMMA GEMM (NT) fp16: C[M,Nf] = A2[M,K2] * B2[Nf,K2]^T  (fp32 accum)
// CTA 128x256, BK=32, 512 threads / 16 warps as 4(m)x4(n), warp tile 32x64,
// 3-stage cp.async pipeline, ONE __syncthreads per iter.
// EPI: 1 = qkv fp16 2-seg pack into Q2/K2/V2; 2 = bias+GELU -> fp16 [hi|lo];
//      3 = bias + residual -> fp32
// ---------------------------------------------------------------------------
#define STG_A_BYTES (128 * 80)            // 10240
#define STG_BYTES   (128 * 80 + 256 * 80) // 30720
#define NSTAGE 3
#define HG_SMEM (NSTAGE * STG_BYTES)      // 92160

template <int EPI>
__global__ __launch_bounds__(512) void hgemm_kernel(
    const __half* __restrict__ A2, const __half* __restrict__ B2,
    const float* __restrict__ bias, const float* __restrict__ resid,
    float* __restrict__ Cf, __half* __restrict__ Cp,
    __half* __restrict__ Q2o, __half* __restrict__ K2o,
    __half* __restrict__ V2o,
    int K2, int ldN)
{
    extern __shared__ __align__(128) char smraw[];
    const uint32_t su = smem_u32(smraw);

    const int tid  = threadIdx.x;
    const int wid  = tid >> 5;
    const int lane = tid & 31;
    const int wm   = wid >> 2;          // 0..3  (32-row slice)
    const int wn   = wid & 3;           // 0..3  (64-col slice)

    const int m0 = blockIdx.y * 128;
    const int n0 = blockIdx.x * 256;

    // A: 4 threads per row (16B each); B: 2 threads per row (32B each)
    const int arow = tid >> 2, aq = tid & 3;
    const int brow = tid >> 1, bhalf = tid & 1;
    const __half* ga = A2 + (size_t)(m0 + arow) * K2 + aq * 8;
    const __half* gb = B2 + (size_t)(n0 + brow) * K2 + bhalf * 16;
    const uint32_t a_st = arow * 80 + aq * 16;
    const uint32_t b_st = STG_A_BYTES + brow * 80 + bhalf * 32;

    const uint32_t lrow  = lane & 15;
    const uint32_t lcolb = (lane >> 4) * 16;
    const uint32_t a_ld  = (wm * 32 + lrow) * 80 + lcolb;
    const uint32_t b_ld  = STG_A_BYTES + (wn * 64 + lrow) * 80 + lcolb;

    float acc[2][8][4];
#pragma unroll
    for (int i = 0; i < 2; i++)
#pragma unroll
        for (int j = 0; j < 8; j++)
#pragma unroll
            for (int v = 0; v < 4; v++) acc[i][j][v] = 0.f;

    const int Tn = K2 / 32;

    // Prologue: stages 0..1
#pragma unroll
    for (int s = 0; s < NSTAGE - 1; s++) {
        const uint32_t sb = su + s * STG_BYTES;
        cp16(sb + a_st, ga + s * 32);
        cp16(sb + b_st,      gb + s * 32);
        cp16(sb + b_st + 16, gb + s * 32 + 8);
        CP_COMMIT();
    }

    int stg_idx = 0;
    for (int t = 0; t < Tn; t++) {
        CP_WAIT1();
        __syncthreads();

        const uint32_t stg = su + stg_idx * STG_BYTES;
        const uint32_t abase = stg + a_ld;
        const uint32_t bbase = stg + b_ld;
#pragma unroll
        for (int ks = 0; ks < 2; ks++) {
            uint32_t af[2][4], bfr[4][4];
            ldsm4(af[0], abase + ks * 32);
            ldsm4(af[1], abase + 16 * 80 + ks * 32);
#pragma unroll
            for (int ni = 0; ni < 4; ni++)
                ldsm4(bfr[ni], bbase + ni * 16 * 80 + ks * 32);
#pragma unroll
            for (int mi = 0; mi < 2; mi++)
#pragma unroll
                for (int ni = 0; ni < 4; ni++) {
                    mma16816h(acc[mi][2 * ni],     af[mi], bfr[ni][0], bfr[ni][2]);
                    mma16816h(acc[mi][2 * ni + 1], af[mi], bfr[ni][1], bfr[ni][3]);
                }
        }

        // Prefetch stage t+2 into the buffer consumed at iter t-1.
        const int tp = t + NSTAGE - 1;
        if (tp < Tn) {
            int pidx = stg_idx + (NSTAGE - 1);
            if (pidx >= NSTAGE) pidx -= NSTAGE;
            const uint32_t sb = su + pidx * STG_BYTES;
            cp16(sb + a_st, ga + tp * 32);
            cp16(sb + b_st,      gb + tp * 32);
            cp16(sb + b_st + 16, gb + tp * 32 + 8);
        }
        CP_COMMIT();   // empty group at tail keeps wait_group bookkeeping exact

        if (++stg_idx == NSTAGE) stg_idx = 0;
    }

    // -------------------- Epilogue --------------------
    const int lm = lane >> 2;
    const int lc = (lane & 3) * 2;

#pragma unroll
    for (int mi = 0; mi < 2; mi++) {
#pragma unroll
        for (int nj = 0; nj < 8; nj++) {
            const int row = m0 + wm * 32 + mi * 16 + lm;
            const int col = n0 + wn * 64 + nj * 8 + lc;
            const float* c = acc[mi][nj];
#pragma unroll
            for (int h = 0; h < 2; h++) {
                const int r = row + h * 8;
                float v0 = c[2 * h], v1 = c[2 * h + 1];
                if (EPI == 3) {
                    const float2 rr = *(const float2*)(resid + (size_t)r * ldN + col);
                    float2 o;
                    o.x = v0 + bias[col]     + rr.x;
                    o.y = v1 + bias[col + 1] + rr.y;
                    *(float2*)(Cf + (size_t)r * ldN + col) = o;
                } else if (EPI == 2) {  // bias + exact GELU -> fp16 [hi|lo]
                    v0 += bias[col];
                    v1 += bias[col + 1];
                    v0 = 0.5f * v0 * (1.0f + erff(v0 * 0.70710678118654752f));
                    v1 = 0.5f * v1 * (1.0f + erff(v1 * 0.70710678118654752f));
                    __half h0, l0, h1, l1;
                    split2h(v0, h0, l0); split2h(v1, h1, l1);
                    __half2 hh, ll;
                    hh.x = h0; hh.y = h1; ll.x = l0; ll.y = l1;
                    __half* rb = Cp + (size_t)r * (2 * (size_t)ldN);
                    *(__half2*)(rb + col)       = hh;
                    *(__half2*)(rb + ldN + col) = ll;
                } else {  // EPI == 1: fp16 2-seg pack of Q/K/V attention operands
                    const int b  = r >> 10, n = r & 1023;
                    const int which = col / 768;
                    const int rem = col - which * 768;
                    const int hh_ = rem >> 6, d = rem & 63;
                    const int bh = b * NHEAD + hh_;
                    __half h0, l0, h1, l1;
                    split2h(v0, h0, l0); split2h(v1, h1, l1);
                    __half2 hp, lp;
                    hp.x = h0; hp.y = h1; lp.x = l0; lp.y = l1;
                    if (which == 0) {          // Q: [hi | lo]
                        __half* base = Q2o + ((size_t)bh * 1024 + n) * KA;
                        *(__half2*)(base + d)      = hp;
                        *(__half2*)(base + 64 + d) = lp;
                    } else if (which == 1) {   // K: [hi | hi]
                        __half* base = K2o + ((size_t)bh * 1024 + n) * KA;
                        *(__half2*)(base + d)      = hp;
                        *(__half2*)(base + 64 + d) = hp;
                    } else {                   // V tile [(bh,kt)][64 d][hi|hi over j]
                        const int kt = n >> 6, j = n & 63;
                        __half* tb = V2o + ((size_t)(bh * 16 + kt) * 64) * KA;
                        __half* r0p = tb + (size_t)d * KA;
                        __half* r1p = r0p + KA;
                        r0p[j] = h0; r0p[64 + j] = h0;
                        r1p[j] = h1; r1p[64 + j] = h1;
                    }
                }
            }
        }
    }
}

// ---------------------------------------------------------------------------
// Tensor-core flash attention, fp16 2-seg (K=128).
// grid (16 qtiles, 192 bh), 128 threads / 4 warps, 68 KB smem (3 CTAs/SM).
// S = [Qhi|Qlo]·[Khi|Khi]^T = Q·fp16(K); O = [Phi|Plo]·[Vhi|Vhi]^T.
// Output packs fp16 [hi|lo] into a2 for the proj GEMM.
// ---------------------------------------------------------------------------
#define ATT_STRIDE 136       // elems per smem row (272 B; 17 banks -> conflict-free)
#define ATT_TILE   (64 * ATT_STRIDE)
#define ATT_SMEM   (4 * ATT_TILE * 2)   // 69632 B

__global__ __launch_bounds__(128) void fattn_kernel(
    const __half* __restrict__ q2, const __half* __restrict__ k2,
    const __half* __restrict__ v2, __half* __restrict__ out2)
{
    extern __shared__ __half sm[];
    __half* Qs = sm;
    __half* Ks = Qs + ATT_TILE;
    __half* Vs = Ks + ATT_TILE;
    __half* Ps = Vs + ATT_TILE;

    const int tid = threadIdx.x, wid = tid >> 5, lane = tid & 31;
    const int qt = blockIdx.x, bh = blockIdx.y;
    const int q0 = qt * 64;

    const uint32_t qs_u = smem_u32(Qs);
    const uint32_t ks_u = smem_u32(Ks);
    const uint32_t vs_u = smem_u32(Vs);

    // Load Q tile once (64 rows x 128 elems): 1024 16B chunks, 8 per thread
    {
        const __half* gQ = q2 + ((size_t)bh * 1024 + q0) * KA;
#pragma unroll
        for (int i = 0; i < 8; i++) {
            const int e = tid + i * 128;
            const int rw = e >> 4, cc = e & 15;
            cp16(qs_u + rw * 272 + cc * 16, gQ + rw * KA + cc * 8);
        }
    }
    CP_COMMIT();

    const uint32_t lrow = lane & 15;
    const uint32_t lcolb = (lane >> 4) * 16;
    const uint32_t a_q = qs_u + (wid * 16 + lrow) * 272 + lcolb;
    const uint32_t a_p = smem_u32(Ps) + (wid * 16 + lrow) * 272 + lcolb;

    float mrun[2] = {-1e30f, -1e30f}, lrun[2] = {0.f, 0.f};
    float accO[8][4];
#pragma unroll
    for (int f = 0; f < 8; f++)
#pragma unroll
        for (int v = 0; v < 4; v++) accO[f][v] = 0.f;

    for (int kt = 0; kt < 16; kt++) {
        __syncthreads();
        {
            const __half* gK = k2 + ((size_t)bh * 1024 + kt * 64) * KA;
            const __half* gV = v2 + ((size_t)(bh * 16 + kt) * 64) * KA;
#pragma unroll
            for (int i = 0; i < 8; i++) {
                const int e = tid + i * 128;
                const int rw = e >> 4, cc = e & 15;
                cp16(ks_u + rw * 272 + cc * 16, gK + rw * KA + cc * 8);
                cp16(vs_u + rw * 272 + cc * 16, gV + rw * KA + cc * 8);
            }
        }
        CP_COMMIT();
        CP_WAIT0();
        __syncthreads();

        // ---- S = Q * K^T (k=128, 8 k16 steps) ----
        float sacc[8][4];
#pragma unroll
        for (int f = 0; f < 8; f++)
#pragma unroll
            for (int v = 0; v < 4; v++) sacc[f][v] = 0.f;
#pragma unroll
        for (int ks = 0; ks < 8; ks++) {
            uint32_t af[4], bfr[4][4];
            ldsm4(af, a_q + ks * 32);
#pragma unroll
            for (int ni = 0; ni < 4; ni++)
                ldsm4(bfr[ni], ks_u + (ni * 16 + lrow) * 272 + lcolb + ks * 32);
#pragma unroll
            for (int ni = 0; ni < 4; ni++) {
                mma16816h(sacc[2 * ni],     af, bfr[ni][0], bfr[ni][2]);
                mma16816h(sacc[2 * ni + 1], af, bfr[ni][1], bfr[ni][3]);
            }
        }
#pragma unroll
        for (int f = 0; f < 8; f++)
#pragma unroll
            for (int v = 0; v < 4; v++) sacc[f][v] *= 0.125f;

        // ---- online softmax (2 rows per thread) ----
#pragma unroll
        for (int hf = 0; hf < 2; hf++) {
            float mt = -1e30f;
#pragma unroll
            for (int f = 0; f < 8; f++)
                mt = fmaxf(mt, fmaxf(sacc[f][2 * hf], sacc[f][2 * hf + 1]));
            mt = fmaxf(mt, __shfl_xor_sync(0xffffffffu, mt, 1));
            mt = fmaxf(mt, __shfl_xor_sync(0xffffffffu, mt, 2));
            const float mnew = fmaxf(mrun[hf], mt);
            const float corr = exp2f((mrun[hf] - mnew) * 1.4426950408889634f);
            float rs = 0.f;
            const int prow = wid * 16 + (lane >> 2) + hf * 8;
            __half* pb = Ps + prow * ATT_STRIDE + (lane & 3) * 2;
#pragma unroll
            for (int f = 0; f < 8; f++) {
                float p0 = exp2f((sacc[f][2 * hf]     - mnew) * 1.4426950408889634f);
                float p1 = exp2f((sacc[f][2 * hf + 1] - mnew) * 1.4426950408889634f);
                rs += p0 + p1;
                __half h0, l0, h1, l1;
                split2h(p0, h0, l0); split2h(p1, h1, l1);
                __half2 hp, lp;
                hp.x = h0; hp.y = h1; lp.x = l0; lp.y = l1;
                *(__half2*)(pb + f * 8)      = hp;   // Phi
                *(__half2*)(pb + 64 + f * 8) = lp;   // Plo
            }
            rs += __shfl_xor_sync(0xffffffffu, rs, 1);
            rs += __shfl_xor_sync(0xffffffffu, rs, 2);
            lrun[hf] = lrun[hf] * corr + rs;
            mrun[hf] = mnew;
#pragma unroll
            for (int f = 0; f < 8; f++) {
                accO[f][2 * hf]     *= corr;
                accO[f][2 * hf + 1] *= corr;
            }
        }
        __syncthreads();

        // ---- O += P * V^T-tile (k=128) ----
#pragma unroll
        for (int ks = 0; ks < 8; ks++) {
            uint32_t af[4], bfr[4][4];
            ldsm4(af, a_p + ks * 32);
#pragma unroll
            for (int ni = 0; ni < 4; ni++)
                ldsm4(bfr[ni], vs_u + (ni * 16 + lrow) * 272 + lcolb + ks * 32);
#pragma unroll
            for (int ni = 0; ni < 4; ni++) {
                mma16816h(accO[2 * ni],     af, bfr[ni][0], bfr[ni][2]);
                mma16816h(accO[2 * ni + 1], af, bfr[ni][1], bfr[ni][3]);
            }
        }
    }

    // Output: fp16 [hi|lo], row length 1536, for the fp16 proj GEMM
    const int b = bh / NHEAD, h = bh - b * NHEAD;
#pragma unroll
    for (int hf = 0; hf < 2; hf++) {
        const float inv = 1.0f / lrun[hf];
        const int t = b * 1024 + q0 + wid * 16 + (lane >> 2) + hf * 8;
        __half* orow = out2 + (size_t)t * K2_D;
        const int cbase = h * 64 + (lane & 3) * 2;
#pragma unroll
        for (int f = 0; f < 8; f++) {
            const float v0 = accO[f][2 * hf] * inv;
            const float v1 = accO[f][2 * hf + 1] * inv;
            __half h0, l0, h1, l1;
            split2h(v0, h0, l0); split2h(v1, h1, l1);
            __half2 hp, lp;
            hp.x = h0; hp.y = h1; lp.x = l0; lp.y = l1;
            const int c = cbase + f * 8;
            *(__half2*)(orow + c)         = hp;
            *(__half2*)(orow + c + D_DIM) = lp;
        }
    }
}

// ---------------------------------------------------------------------------
// Launch
// ---------------------------------------------------------------------------
extern "C" void kernel_launch(void* const* d_in, const int* in_sizes, int n_in,
                              void* d_out, int out_size)
{
    const float* x      = (const float*)d_in[0];
    const float* qkv_w  = (const float*)d_in[1];
    const float* proj_w = (const float*)d_in[2];
    const float* proj_b = (const float*)d_in[3];
    const float* fc1_w  = (const float*)d_in[4];
    const float* fc1_b  = (const float*)d_in[5];
    const float* fc2_w  = (const float*)d_in[6];
    const float* fc2_b  = (const float*)d_in[7];
    const float* n1g    = (const float*)d_in[8];
    const float* n1b    = (const float*)d_in[9];
    const float* n2g    = (const float*)d_in[10];
    const float* n2b    = (const float*)d_in[11];
    float* out = (float*)d_out;

    void *pa2, *ph2, *pq2, *pk2, *pv2, *pwq, *pwp, *pw1, *pw2;
    cudaGetSymbolAddress(&pa2, g_a2);
    cudaGetSymbolAddress(&ph2, g_h2);
    cudaGetSymbolAddress(&pq2, g_q2);
    cudaGetSymbolAddress(&pk2, g_k2);
    cudaGetSymbolAddress(&pv2, g_v2);
    cudaGetSymbolAddress(&pwq, g_wqkv2);
    cudaGetSymbolAddress(&pwp, g_wproj2);
    cudaGetSymbolAddress(&pw1, g_wfc12);
    cudaGetSymbolAddress(&pw2, g_wfc22);
    __half* a2  = (__half*)pa2;
    __half* h2  = (__half*)ph2;
    __half* q2  = (__half*)pq2;
    __half* k2  = (__half*)pk2;
    __half* v2  = (__half*)pv2;
    __half* wq2 = (__half*)pwq;
    __half* wp2 = (__half*)pwp;
    __half* w12 = (__half*)pw1;
    __half* w22 = (__half*)pw2;

    cudaFuncSetAttribute(hgemm_kernel<1>, cudaFuncAttributeMaxDynamicSharedMemorySize, HG_SMEM);
    cudaFuncSetAttribute(hgemm_kernel<2>, cudaFuncAttributeMaxDynamicSharedMemorySize, HG_SMEM);
    cudaFuncSetAttribute(hgemm_kernel<3>, cudaFuncAttributeMaxDynamicSharedMemorySize, HG_SMEM);
    cudaFuncSetAttribute(fattn_kernel, cudaFuncAttributeMaxDynamicSharedMemorySize, ATT_SMEM);

    // 0) pack weights (fp16 [hi|hi] along K)
    pack_w_kernel<<<(QKV_N * D_DIM + 255) / 256, 256>>>(qkv_w,  wq2, QKV_N * D_DIM,  D_DIM);
    pack_w_kernel<<<(D_DIM * D_DIM + 255) / 256, 256>>>(proj_w, wp2, D_DIM * D_DIM,  D_DIM);
    pack_w_kernel<<<(HID_DIM * D_DIM + 255) / 256, 256>>>(fc1_w, w12, HID_DIM * D_DIM, D_DIM);
    pack_w_kernel<<<(D_DIM * HID_DIM + 255) / 256, 256>>>(fc2_w, w22, D_DIM * HID_DIM, HID_DIM);

    // 1) LN1 + fp16 pack [hi|lo]
    ln_pack_kernel<<<T_TOK, 256>>>(x, n1g, n1b, a2);
    // 2) QKV GEMM (fp16) -> fp16 2-seg packed Q2/K2/V2 attention operands
    hgemm_kernel<1><<<dim3(QKV_N / 256, T_TOK / 128), 512, HG_SMEM>>>(
        a2, wq2, nullptr, nullptr, nullptr, nullptr, q2, k2, v2, K2_D, QKV_N);
    // 3) tensor-core flash attention (fp16 2-seg) -> fp16 packed a2
    fattn_kernel<<<dim3(16, BH), 128, ATT_SMEM>>>(q2, k2, v2, a2);
    // 4) x1 = x + attn @ proj_w^T + proj_b -> d_out
    hgemm_kernel<3><<<dim3(D_DIM / 256, T_TOK / 128), 512, HG_SMEM>>>(
        a2, wp2, proj_b, x, out, nullptr, nullptr, nullptr, nullptr, K2_D, D_DIM);
    // 5) LN2 + fp16 pack
    ln_pack_kernel<<<T_TOK, 256>>>(out, n2g, n2b, a2);
    // 6) h2 = fp16-pack(gelu(ln2 @ fc1_w^T + fc1_b))
    hgemm_kernel<2><<<dim3(HID_DIM / 256, T_TOK / 128), 512, HG_SMEM>>>(
        a2, w12, fc1_b, nullptr, nullptr, h2, nullptr, nullptr, nullptr, K2_D, HID_DIM);
    // 7) out = x1 + h @ fc2_w^T + fc2_b (in-place residual)
    hgemm_kernel<3><<<dim3(D_DIM / 256, T_TOK / 128), 512, HG_SMEM>>>(
        h2, w22, fc2_b, out, out, nullptr, nullptr, nullptr, nullptr, K2_H, D_DIM);
}